// round 1
// baseline (speedup 1.0000x reference)
#include <cuda_runtime.h>

#define BB 8
#define CC 64
#define NN 4096
#define PITCH 68   // floats per smem row: 68*4=272 bytes, 16B aligned, conflict-free

// Scratch (allocation-free rule: __device__ globals)
__device__ float g_q[BB*NN*CC];
__device__ float g_k[BB*NN*CC];
__device__ float g_v[BB*NN*CC];
__device__ float g_res[BB*NN*CC];
__device__ float g_m[BB*NN];
__device__ float g_zi[BB*NN];

#define LD4(p) (*(const float4*)(p))

// ------------------------------------------------------------------
// Kernel 1: q,k,v = W{q,k,v} @ x + b, stored transposed as (B, N, C)
// grid (NN/64, BB), 256 threads
// ------------------------------------------------------------------
__global__ void qkv_kernel(const float* __restrict__ x,
                           const float* __restrict__ Wq, const float* __restrict__ bq,
                           const float* __restrict__ Wk, const float* __restrict__ bk,
                           const float* __restrict__ Wv, const float* __restrict__ bv)
{
    extern __shared__ float sm[];
    float* ws = sm;                 // [3][CC][PITCH], ws[m][cin][cout] = W[cout][cin]
    float* xs = sm + 3*CC*PITCH;    // [CC][64], xs[cin][n]
    const int b  = blockIdx.y;
    const int n0 = blockIdx.x * 64;
    const int t  = threadIdx.x;

    const float* Wmats[3] = {Wq, Wk, Wv};
    #pragma unroll
    for (int m = 0; m < 3; m++)
        for (int idx = t; idx < CC*CC; idx += 256) {
            int cout = idx >> 6, cin = idx & 63;
            ws[(m*CC + cin)*PITCH + cout] = Wmats[m][idx];
        }
    for (int idx = t; idx < CC*64; idx += 256) {
        int cin = idx >> 6, n = idx & 63;
        xs[cin*64 + n] = x[(b*CC + cin)*NN + n0 + n];
    }
    __syncthreads();

    const int tx = t & 15, ty = t >> 4;   // cout = 4*tx+j, n = ty + 16*k
    float acc[3][4][4];
    #pragma unroll
    for (int m = 0; m < 3; m++)
        #pragma unroll
        for (int k = 0; k < 4; k++)
            #pragma unroll
            for (int j = 0; j < 4; j++) acc[m][k][j] = 0.f;

    #pragma unroll 4
    for (int ci = 0; ci < CC; ci++) {
        float xv[4];
        #pragma unroll
        for (int k = 0; k < 4; k++) xv[k] = xs[ci*64 + ty + 16*k];
        #pragma unroll
        for (int m = 0; m < 3; m++) {
            const float4 w4 = LD4(&ws[(m*CC + ci)*PITCH + 4*tx]);
            #pragma unroll
            for (int k = 0; k < 4; k++) {
                acc[m][k][0] = fmaf(xv[k], w4.x, acc[m][k][0]);
                acc[m][k][1] = fmaf(xv[k], w4.y, acc[m][k][1]);
                acc[m][k][2] = fmaf(xv[k], w4.z, acc[m][k][2]);
                acc[m][k][3] = fmaf(xv[k], w4.w, acc[m][k][3]);
            }
        }
    }

    const float* biases[3] = {bq, bk, bv};
    float* outs[3] = {g_q, g_k, g_v};
    #pragma unroll
    for (int m = 0; m < 3; m++) {
        const float4 bb = LD4(&biases[m][4*tx]);
        #pragma unroll
        for (int k = 0; k < 4; k++) {
            int n = n0 + ty + 16*k;
            float4 o;
            o.x = acc[m][k][0] + bb.x;
            o.y = acc[m][k][1] + bb.y;
            o.z = acc[m][k][2] + bb.z;
            o.w = acc[m][k][3] + bb.w;
            *(float4*)&outs[m][(b*NN + n)*CC + 4*tx] = o;
        }
    }
}

// ------------------------------------------------------------------
// Kernel 2a: for each row j: M_j = max_i s[j,i], Z_j = sum_i exp(s-M)
// s[j,i] = q_j . k_i.   grid (NN/64, BB), 128 threads
// ------------------------------------------------------------------
__global__ void attn_stats_kernel()
{
    extern __shared__ float sm[];
    float* Qt = sm;               // [CC][PITCH], Qt[d][j]
    float* Kt = Qt + CC*PITCH;    // [CC][PITCH], Kt[d][i]
    float* Ss = Kt + CC*PITCH;    // [64][PITCH], Ss[j][i]
    const int b  = blockIdx.y;
    const int j0 = blockIdx.x * 64;
    const int t  = threadIdx.x;
    const int tx = t & 15, ty = t >> 4;   // j = 8*ty+r, i = 4*tx+c

    for (int idx = t; idx < 1024; idx += 128) {
        int cg = idx >> 6, n = idx & 63;
        float4 v = LD4(&g_q[(b*NN + j0 + n)*CC + 4*cg]);
        Qt[(4*cg+0)*PITCH + n] = v.x;
        Qt[(4*cg+1)*PITCH + n] = v.y;
        Qt[(4*cg+2)*PITCH + n] = v.z;
        Qt[(4*cg+3)*PITCH + n] = v.w;
    }
    float m_run = -3.0e38f, l_run = 0.f;

    for (int ib = 0; ib < NN/64; ib++) {
        const int i0 = ib*64;
        __syncthreads();
        for (int idx = t; idx < 1024; idx += 128) {
            int cg = idx >> 6, n = idx & 63;
            float4 v = LD4(&g_k[(b*NN + i0 + n)*CC + 4*cg]);
            Kt[(4*cg+0)*PITCH + n] = v.x;
            Kt[(4*cg+1)*PITCH + n] = v.y;
            Kt[(4*cg+2)*PITCH + n] = v.z;
            Kt[(4*cg+3)*PITCH + n] = v.w;
        }
        __syncthreads();

        float S[8][4];
        #pragma unroll
        for (int r = 0; r < 8; r++)
            #pragma unroll
            for (int c = 0; c < 4; c++) S[r][c] = 0.f;

        #pragma unroll 4
        for (int d = 0; d < CC; d++) {
            const float4 kk = LD4(&Kt[d*PITCH + 4*tx]);
            const float4 qa = LD4(&Qt[d*PITCH + 8*ty]);
            const float4 qb = LD4(&Qt[d*PITCH + 8*ty + 4]);
            const float q8[8] = {qa.x,qa.y,qa.z,qa.w,qb.x,qb.y,qb.z,qb.w};
            const float k4[4] = {kk.x,kk.y,kk.z,kk.w};
            #pragma unroll
            for (int r = 0; r < 8; r++)
                #pragma unroll
                for (int c = 0; c < 4; c++)
                    S[r][c] = fmaf(q8[r], k4[c], S[r][c]);
        }
        #pragma unroll
        for (int r = 0; r < 8; r++)
            *(float4*)&Ss[(8*ty+r)*PITCH + 4*tx] =
                make_float4(S[r][0], S[r][1], S[r][2], S[r][3]);
        __syncthreads();

        if (t < 64) {
            const float* row = &Ss[t*PITCH];
            float mx = m_run;
            #pragma unroll 4
            for (int jj = 0; jj < 64; jj += 4) {
                float4 s4 = LD4(&row[jj]);
                mx = fmaxf(mx, fmaxf(fmaxf(s4.x, s4.y), fmaxf(s4.z, s4.w)));
            }
            float ls = l_run * __expf(m_run - mx);
            #pragma unroll 4
            for (int jj = 0; jj < 64; jj += 4) {
                float4 s4 = LD4(&row[jj]);
                ls += __expf(s4.x - mx) + __expf(s4.y - mx)
                    + __expf(s4.z - mx) + __expf(s4.w - mx);
            }
            m_run = mx; l_run = ls;
        }
    }
    if (t < 64) {
        g_m[b*NN + j0 + t]  = m_run;
        g_zi[b*NN + j0 + t] = 1.0f / l_run;
    }
}

// ------------------------------------------------------------------
// Kernel 2b: O[i,c] = sum_j exp(s[j,i]-M_j)*zi_j * v[j,c]
// grid (NN/64, BB) over i-tiles, 128 threads
// ------------------------------------------------------------------
__global__ void attn_apply_kernel()
{
    extern __shared__ float sm[];
    float* Kt   = sm;                // [CC][PITCH], Kt[d][i]   (i-tile, loaded once)
    float* Qt   = Kt + CC*PITCH;     // [CC][PITCH], Qt[d][j]
    float* Vs   = Qt + CC*PITCH;     // [64][PITCH], Vs[j][c]
    float* Ps   = Vs + 64*PITCH;     // [64][PITCH], Ps[j][i]
    float* mrow = Ps + 64*PITCH;     // [64]
    float* zrow = mrow + 64;         // [64]
    const int b  = blockIdx.y;
    const int i0 = blockIdx.x * 64;
    const int t  = threadIdx.x;
    const int tx = t & 15, ty = t >> 4;

    for (int idx = t; idx < 1024; idx += 128) {
        int cg = idx >> 6, n = idx & 63;
        float4 v = LD4(&g_k[(b*NN + i0 + n)*CC + 4*cg]);
        Kt[(4*cg+0)*PITCH + n] = v.x;
        Kt[(4*cg+1)*PITCH + n] = v.y;
        Kt[(4*cg+2)*PITCH + n] = v.z;
        Kt[(4*cg+3)*PITCH + n] = v.w;
    }

    float O[8][4];
    #pragma unroll
    for (int r = 0; r < 8; r++)
        #pragma unroll
        for (int c = 0; c < 4; c++) O[r][c] = 0.f;

    for (int jb = 0; jb < NN/64; jb++) {
        const int j0 = jb*64;
        __syncthreads();
        for (int idx = t; idx < 1024; idx += 128) {
            int cg = idx >> 6, n = idx & 63;
            float4 v = LD4(&g_q[(b*NN + j0 + n)*CC + 4*cg]);
            Qt[(4*cg+0)*PITCH + n] = v.x;
            Qt[(4*cg+1)*PITCH + n] = v.y;
            Qt[(4*cg+2)*PITCH + n] = v.z;
            Qt[(4*cg+3)*PITCH + n] = v.w;
        }
        for (int idx = t; idx < 1024; idx += 128) {
            int n = idx >> 4, cg = idx & 15;
            *(float4*)&Vs[n*PITCH + 4*cg] = LD4(&g_v[(b*NN + j0 + n)*CC + 4*cg]);
        }
        if (t < 64) {
            mrow[t] = g_m[b*NN + j0 + t];
            zrow[t] = g_zi[b*NN + j0 + t];
        }
        __syncthreads();

        // T[j,i] fragment: j = 8*ty+r, i = 4*tx+c
        float S[8][4];
        #pragma unroll
        for (int r = 0; r < 8; r++)
            #pragma unroll
            for (int c = 0; c < 4; c++) S[r][c] = 0.f;

        #pragma unroll 4
        for (int d = 0; d < CC; d++) {
            const float4 kk = LD4(&Kt[d*PITCH + 4*tx]);
            const float4 qa = LD4(&Qt[d*PITCH + 8*ty]);
            const float4 qb = LD4(&Qt[d*PITCH + 8*ty + 4]);
            const float q8[8] = {qa.x,qa.y,qa.z,qa.w,qb.x,qb.y,qb.z,qb.w};
            const float k4[4] = {kk.x,kk.y,kk.z,kk.w};
            #pragma unroll
            for (int r = 0; r < 8; r++)
                #pragma unroll
                for (int c = 0; c < 4; c++)
                    S[r][c] = fmaf(q8[r], k4[c], S[r][c]);
        }
        #pragma unroll
        for (int r = 0; r < 8; r++) {
            const float mj = mrow[8*ty + r];
            const float zj = zrow[8*ty + r];
            float4 p;
            p.x = __expf(S[r][0] - mj) * zj;
            p.y = __expf(S[r][1] - mj) * zj;
            p.z = __expf(S[r][2] - mj) * zj;
            p.w = __expf(S[r][3] - mj) * zj;
            *(float4*)&Ps[(8*ty+r)*PITCH + 4*tx] = p;
        }
        __syncthreads();

        // O[i,c] += Ps[j][i] * Vs[j][c]; i = 8*ty+r, c = 4*tx+cc
        #pragma unroll 4
        for (int j = 0; j < 64; j++) {
            const float4 v4 = LD4(&Vs[j*PITCH + 4*tx]);
            const float4 pa = LD4(&Ps[j*PITCH + 8*ty]);
            const float4 pb = LD4(&Ps[j*PITCH + 8*ty + 4]);
            const float p8[8] = {pa.x,pa.y,pa.z,pa.w,pb.x,pb.y,pb.z,pb.w};
            const float vv[4] = {v4.x,v4.y,v4.z,v4.w};
            #pragma unroll
            for (int r = 0; r < 8; r++)
                #pragma unroll
                for (int c = 0; c < 4; c++)
                    O[r][c] = fmaf(p8[r], vv[c], O[r][c]);
        }
    }

    #pragma unroll
    for (int r = 0; r < 8; r++)
        *(float4*)&g_res[(b*NN + i0 + 8*ty + r)*CC + 4*tx] =
            make_float4(O[r][0], O[r][1], O[r][2], O[r][3]);
}

// ------------------------------------------------------------------
// Kernel 3: out = Wo @ res + bo + res, out is (B,C,H,W)
// grid (NN/64, BB), 256 threads
// ------------------------------------------------------------------
__global__ void out_kernel(const float* __restrict__ Wo, const float* __restrict__ bo,
                           float* __restrict__ out)
{
    __shared__ float ws[CC*PITCH];    // ws[cin][cout] = Wo[cout][cin]
    __shared__ float rst[CC*PITCH];   // rst[c][n]
    const int b  = blockIdx.y;
    const int n0 = blockIdx.x * 64;
    const int t  = threadIdx.x;

    for (int idx = t; idx < CC*CC; idx += 256) {
        int cout = idx >> 6, cin = idx & 63;
        ws[cin*PITCH + cout] = Wo[idx];
    }
    for (int idx = t; idx < 1024; idx += 256) {
        int cg = idx >> 6, n = idx & 63;
        float4 v = LD4(&g_res[(b*NN + n0 + n)*CC + 4*cg]);
        rst[(4*cg+0)*PITCH + n] = v.x;
        rst[(4*cg+1)*PITCH + n] = v.y;
        rst[(4*cg+2)*PITCH + n] = v.z;
        rst[(4*cg+3)*PITCH + n] = v.w;
    }
    __syncthreads();

    const int tx = t & 15, ty = t >> 4;   // n = 4*tx+j, c = ty + 16*k
    float acc[4][4];
    #pragma unroll
    for (int k = 0; k < 4; k++)
        #pragma unroll
        for (int j = 0; j < 4; j++) acc[k][j] = 0.f;

    #pragma unroll 4
    for (int ci = 0; ci < CC; ci++) {
        const float4 r4 = LD4(&rst[ci*PITCH + 4*tx]);
        float wv[4];
        #pragma unroll
        for (int k = 0; k < 4; k++) wv[k] = ws[ci*PITCH + ty + 16*k];
        #pragma unroll
        for (int k = 0; k < 4; k++) {
            acc[k][0] = fmaf(wv[k], r4.x, acc[k][0]);
            acc[k][1] = fmaf(wv[k], r4.y, acc[k][1]);
            acc[k][2] = fmaf(wv[k], r4.z, acc[k][2]);
            acc[k][3] = fmaf(wv[k], r4.w, acc[k][3]);
        }
    }

    #pragma unroll
    for (int k = 0; k < 4; k++) {
        int c = ty + 16*k;
        float bv = bo[c];
        float4 resid = LD4(&rst[c*PITCH + 4*tx]);
        float4 o;
        o.x = acc[k][0] + bv + resid.x;
        o.y = acc[k][1] + bv + resid.y;
        o.z = acc[k][2] + bv + resid.z;
        o.w = acc[k][3] + bv + resid.w;
        *(float4*)&out[(b*CC + c)*NN + n0 + 4*tx] = o;
    }
}

// ------------------------------------------------------------------
extern "C" void kernel_launch(void* const* d_in, const int* in_sizes, int n_in,
                              void* d_out, int out_size)
{
    const float* x  = (const float*)d_in[0];
    const float* Wq = (const float*)d_in[1];
    const float* bq = (const float*)d_in[2];
    const float* Wk = (const float*)d_in[3];
    const float* bk = (const float*)d_in[4];
    const float* Wv = (const float*)d_in[5];
    const float* bv = (const float*)d_in[6];
    const float* Wo = (const float*)d_in[7];
    const float* bo = (const float*)d_in[8];
    float* out = (float*)d_out;

    const int QKV_SMEM   = (3*CC*PITCH + CC*64) * 4;
    const int STATS_SMEM = (3*64*PITCH) * 4;
    const int APPLY_SMEM = (4*64*PITCH + 128) * 4;

    cudaFuncSetAttribute(qkv_kernel,        cudaFuncAttributeMaxDynamicSharedMemorySize, QKV_SMEM);
    cudaFuncSetAttribute(attn_stats_kernel, cudaFuncAttributeMaxDynamicSharedMemorySize, STATS_SMEM);
    cudaFuncSetAttribute(attn_apply_kernel, cudaFuncAttributeMaxDynamicSharedMemorySize, APPLY_SMEM);

    dim3 grid(NN/64, BB);
    qkv_kernel<<<grid, 256, QKV_SMEM>>>(x, Wq, bq, Wk, bk, Wv, bv);
    attn_stats_kernel<<<grid, 128, STATS_SMEM>>>();
    attn_apply_kernel<<<grid, 128, APPLY_SMEM>>>();
    out_kernel<<<grid, 256>>>(Wo, bo, out);
}

// round 3
// speedup vs baseline: 3.0292x; 3.0292x over previous
#include <cuda_runtime.h>
#include <cuda_bf16.h>
#include <cstdint>

#define BB 8
#define CC 64
#define NN 4096
#define PITCH 68      // fp32 smem pitch for qkv/out kernels
#define BPITCH 144    // bf16 tile row pitch in BYTES (72 elems): conflict-free ldmatrix

// ---------------- scratch ----------------
__device__ __nv_bfloat16 g_qh[BB*NN*CC], g_ql[BB*NN*CC];
__device__ __nv_bfloat16 g_kh[BB*NN*CC], g_kl[BB*NN*CC];
__device__ __nv_bfloat16 g_vh[BB*NN*CC], g_vl[BB*NN*CC];
__device__ float g_res[BB*NN*CC];
__device__ float g_zi[BB*NN];

#define LD4(p) (*(const float4*)(p))

__device__ __forceinline__ uint32_t smem_to_u32(const void* p) {
    uint32_t a;
    asm("{ .reg .u64 t; cvta.to.shared.u64 t, %1; cvt.u32.u64 %0, t; }" : "=r"(a) : "l"(p));
    return a;
}
__device__ __forceinline__ void ldsm4(uint32_t addr, uint32_t* r) {
    asm volatile("ldmatrix.sync.aligned.m8n8.x4.shared.b16 {%0,%1,%2,%3}, [%4];"
                 : "=r"(r[0]), "=r"(r[1]), "=r"(r[2]), "=r"(r[3]) : "r"(addr));
}
__device__ __forceinline__ void ldsm4t(uint32_t addr, uint32_t* r) {
    asm volatile("ldmatrix.sync.aligned.m8n8.x4.trans.shared.b16 {%0,%1,%2,%3}, [%4];"
                 : "=r"(r[0]), "=r"(r[1]), "=r"(r[2]), "=r"(r[3]) : "r"(addr));
}
__device__ __forceinline__ void mma16816(float* c, const uint32_t* a, uint32_t b0, uint32_t b1) {
    asm volatile("mma.sync.aligned.m16n8k16.row.col.f32.bf16.bf16.f32 "
                 "{%0,%1,%2,%3}, {%4,%5,%6,%7}, {%8,%9}, {%0,%1,%2,%3};"
                 : "+f"(c[0]), "+f"(c[1]), "+f"(c[2]), "+f"(c[3])
                 : "r"(a[0]), "r"(a[1]), "r"(a[2]), "r"(a[3]), "r"(b0), "r"(b1));
}
// split two fp32 into bf16 hi-pair and lo-pair (packed b32, elem0 in low half)
__device__ __forceinline__ void split2(float p0, float p1, uint32_t& h, uint32_t& l) {
    __nv_bfloat16 h0 = __float2bfloat16_rn(p0), h1 = __float2bfloat16_rn(p1);
    float l0f = p0 - __bfloat162float(h0), l1f = p1 - __bfloat162float(h1);
    __nv_bfloat16 l0 = __float2bfloat16_rn(l0f), l1 = __float2bfloat16_rn(l1f);
    h = ((uint32_t)__bfloat16_as_ushort(h1) << 16) | __bfloat16_as_ushort(h0);
    l = ((uint32_t)__bfloat16_as_ushort(l1) << 16) | __bfloat16_as_ushort(l0);
}

// ldmatrix address helpers (smem tiles row-major, BPITCH bytes/row)
// A fragment m16k16 at (r0,c0): group g: row r0+lr+(g&1)*8, col c0+(g>>1)*8
__device__ __forceinline__ uint32_t addrA(uint32_t base, int r0, int c0, int lr, int g) {
    return base + (uint32_t)(r0 + lr + ((g & 1) << 3)) * BPITCH + ((uint32_t)(c0 + ((g >> 1) << 3)) << 1);
}
// B fragments (col-major, k-contig rows): x4 covers ksteps {k0..k0+31}, rows n0..n0+7
__device__ __forceinline__ uint32_t addrB(uint32_t base, int n0, int k0, int lr, int g) {
    return base + (uint32_t)(n0 + lr) * BPITCH + ((uint32_t)(k0 + g * 8) << 1);
}
// B fragments via trans (stored [k][n]): x4 covers k0..k0+31 rows, col n0
__device__ __forceinline__ uint32_t addrBt(uint32_t base, int k0, int n0, int lr, int g) {
    return base + (uint32_t)(k0 + g * 8 + lr) * BPITCH + ((uint32_t)n0 << 1);
}

// ------------------------------------------------------------------
// Kernel 1: q,k,v = W @ x + b -> bf16 hi/lo planes, layout [b][n][c]
// grid (NN/64, BB), 256 threads
// ------------------------------------------------------------------
__global__ void qkv_kernel(const float* __restrict__ x,
                           const float* __restrict__ Wq, const float* __restrict__ bq,
                           const float* __restrict__ Wk, const float* __restrict__ bk,
                           const float* __restrict__ Wv, const float* __restrict__ bv)
{
    extern __shared__ float smf[];
    float* ws = smf;
    float* xs = smf + 3*CC*PITCH;
    const int b  = blockIdx.y;
    const int n0 = blockIdx.x * 64;
    const int t  = threadIdx.x;

    const float* Wmats[3] = {Wq, Wk, Wv};
    #pragma unroll
    for (int m = 0; m < 3; m++)
        for (int idx = t; idx < CC*CC; idx += 256) {
            int cout = idx >> 6, cin = idx & 63;
            ws[(m*CC + cin)*PITCH + cout] = Wmats[m][idx];
        }
    for (int idx = t; idx < CC*64; idx += 256) {
        int cin = idx >> 6, n = idx & 63;
        xs[cin*64 + n] = x[(size_t)(b*CC + cin)*NN + n0 + n];
    }
    __syncthreads();

    const int tx = t & 15, ty = t >> 4;
    float acc[3][4][4];
    #pragma unroll
    for (int m = 0; m < 3; m++)
        #pragma unroll
        for (int k = 0; k < 4; k++)
            #pragma unroll
            for (int j = 0; j < 4; j++) acc[m][k][j] = 0.f;

    #pragma unroll 4
    for (int ci = 0; ci < CC; ci++) {
        float xv[4];
        #pragma unroll
        for (int k = 0; k < 4; k++) xv[k] = xs[ci*64 + ty + 16*k];
        #pragma unroll
        for (int m = 0; m < 3; m++) {
            const float4 w4 = LD4(&ws[(m*CC + ci)*PITCH + 4*tx]);
            #pragma unroll
            for (int k = 0; k < 4; k++) {
                acc[m][k][0] = fmaf(xv[k], w4.x, acc[m][k][0]);
                acc[m][k][1] = fmaf(xv[k], w4.y, acc[m][k][1]);
                acc[m][k][2] = fmaf(xv[k], w4.z, acc[m][k][2]);
                acc[m][k][3] = fmaf(xv[k], w4.w, acc[m][k][3]);
            }
        }
    }

    const float* biases[3] = {bq, bk, bv};
    __nv_bfloat16* outsH[3] = {g_qh, g_kh, g_vh};
    __nv_bfloat16* outsL[3] = {g_ql, g_kl, g_vl};
    #pragma unroll
    for (int m = 0; m < 3; m++) {
        const float4 bb4 = LD4(&biases[m][4*tx]);
        const float bbv[4] = {bb4.x, bb4.y, bb4.z, bb4.w};
        #pragma unroll
        for (int k = 0; k < 4; k++) {
            int n = n0 + ty + 16*k;
            uint32_t Hp[2], Lp[2];
            #pragma unroll
            for (int jp = 0; jp < 2; jp++) {
                float v0 = acc[m][k][2*jp]   + bbv[2*jp];
                float v1 = acc[m][k][2*jp+1] + bbv[2*jp+1];
                split2(v0, v1, Hp[jp], Lp[jp]);
            }
            size_t idx = (size_t)(b*NN + n)*CC + 4*tx;
            *reinterpret_cast<uint2*>(&outsH[m][idx]) = make_uint2(Hp[0], Hp[1]);
            *reinterpret_cast<uint2*>(&outsL[m][idx]) = make_uint2(Lp[0], Lp[1]);
        }
    }
}

// ------------------------------------------------------------------
// Kernel 2: Z_j = sum_i exp(q_j . k_i)  ->  g_zi = 1/Z
// grid (NN/128, BB), 256 threads (8 warps, each 16 j-rows)
// ------------------------------------------------------------------
#define SH_QH 0
#define SH_QL 18432
#define SH_KH 36864
#define SH_KL 46080
#define ST_SMEM 55296

__global__ void __launch_bounds__(256) stats_kernel()
{
    extern __shared__ char smc[];
    const uint32_t sb = smem_to_u32(smc);
    const int b = blockIdx.y, j0 = blockIdx.x * 128;
    const int t = threadIdx.x, w = t >> 5, lane = t & 31;
    const int lr = lane & 7, g = lane >> 3, qr = lane >> 2, qc = lane & 3;

    {   // load Q tile: 128 rows x 64 bf16 (hi+lo)
        const __nv_bfloat16* sH = &g_qh[(size_t)(b*NN + j0)*CC];
        const __nv_bfloat16* sL = &g_ql[(size_t)(b*NN + j0)*CC];
        for (int idx = t; idx < 1024; idx += 256) {
            int row = idx >> 3, seg = idx & 7;
            *(uint4*)(smc + SH_QH + row*BPITCH + seg*16) = *(const uint4*)&sH[row*64 + seg*8];
            *(uint4*)(smc + SH_QL + row*BPITCH + seg*16) = *(const uint4*)&sL[row*64 + seg*8];
        }
    }
    __syncthreads();

    uint32_t Ah[4][4], Al[4][4];
    #pragma unroll
    for (int ks = 0; ks < 4; ks++) {
        ldsm4(addrA(sb + SH_QH, w*16, ks*16, lr, g), Ah[ks]);
        ldsm4(addrA(sb + SH_QL, w*16, ks*16, lr, g), Al[ks]);
    }

    float zacc0 = 0.f, zacc1 = 0.f;

    for (int it = 0; it < NN/64; it++) {
        __syncthreads();
        {
            const __nv_bfloat16* sH = &g_kh[(size_t)(b*NN + it*64)*CC];
            const __nv_bfloat16* sL = &g_kl[(size_t)(b*NN + it*64)*CC];
            for (int idx = t; idx < 512; idx += 256) {
                int row = idx >> 3, seg = idx & 7;
                *(uint4*)(smc + SH_KH + row*BPITCH + seg*16) = *(const uint4*)&sH[row*64 + seg*8];
                *(uint4*)(smc + SH_KL + row*BPITCH + seg*16) = *(const uint4*)&sL[row*64 + seg*8];
            }
        }
        __syncthreads();

        #pragma unroll
        for (int nt = 0; nt < 8; nt++) {
            uint32_t bh[8], bl[8];
            ldsm4(addrB(sb + SH_KH, nt*8,  0, lr, g), bh);
            ldsm4(addrB(sb + SH_KH, nt*8, 32, lr, g), bh + 4);
            ldsm4(addrB(sb + SH_KL, nt*8,  0, lr, g), bl);
            ldsm4(addrB(sb + SH_KL, nt*8, 32, lr, g), bl + 4);
            float C[4] = {0.f, 0.f, 0.f, 0.f};
            #pragma unroll
            for (int ks = 0; ks < 4; ks++) mma16816(C, Ah[ks], bh[2*ks], bh[2*ks+1]);
            #pragma unroll
            for (int ks = 0; ks < 4; ks++) mma16816(C, Ah[ks], bl[2*ks], bl[2*ks+1]);
            #pragma unroll
            for (int ks = 0; ks < 4; ks++) mma16816(C, Al[ks], bh[2*ks], bh[2*ks+1]);
            zacc0 += __expf(C[0]) + __expf(C[1]);
            zacc1 += __expf(C[2]) + __expf(C[3]);
        }
    }

    zacc0 += __shfl_xor_sync(0xffffffffu, zacc0, 1);
    zacc0 += __shfl_xor_sync(0xffffffffu, zacc0, 2);
    zacc1 += __shfl_xor_sync(0xffffffffu, zacc1, 1);
    zacc1 += __shfl_xor_sync(0xffffffffu, zacc1, 2);
    if (qc == 0) {
        g_zi[b*NN + j0 + w*16 + qr]     = 1.f / zacc0;
        g_zi[b*NN + j0 + w*16 + qr + 8] = 1.f / zacc1;
    }
}

// ------------------------------------------------------------------
// Kernel 3: O[i,c] = sum_j exp(k_i . q_j) * zi_j * v[j,c]
// grid (NN/128, BB), 256 threads (8 warps, each 16 i-rows)
// ------------------------------------------------------------------
#define AH_KH 0
#define AH_KL 18432
#define AH_QH 36864
#define AH_QL 46080
#define AH_VH 55296
#define AH_VL 64512
#define AH_ZR 73728
#define AP_SMEM 73984

__global__ void __launch_bounds__(256) apply_kernel()
{
    extern __shared__ char smc[];
    const uint32_t sb = smem_to_u32(smc);
    float* zr = reinterpret_cast<float*>(smc + AH_ZR);
    const int b = blockIdx.y, i0 = blockIdx.x * 128;
    const int t = threadIdx.x, w = t >> 5, lane = t & 31;
    const int lr = lane & 7, g = lane >> 3, qr = lane >> 2, qc = lane & 3;

    {   // K tile: 128 rows (i)
        const __nv_bfloat16* sH = &g_kh[(size_t)(b*NN + i0)*CC];
        const __nv_bfloat16* sL = &g_kl[(size_t)(b*NN + i0)*CC];
        for (int idx = t; idx < 1024; idx += 256) {
            int row = idx >> 3, seg = idx & 7;
            *(uint4*)(smc + AH_KH + row*BPITCH + seg*16) = *(const uint4*)&sH[row*64 + seg*8];
            *(uint4*)(smc + AH_KL + row*BPITCH + seg*16) = *(const uint4*)&sL[row*64 + seg*8];
        }
    }
    __syncthreads();

    uint32_t KAh[4][4], KAl[4][4];
    #pragma unroll
    for (int ks = 0; ks < 4; ks++) {
        ldsm4(addrA(sb + AH_KH, w*16, ks*16, lr, g), KAh[ks]);
        ldsm4(addrA(sb + AH_KL, w*16, ks*16, lr, g), KAl[ks]);
    }

    float O[8][4];
    #pragma unroll
    for (int cn = 0; cn < 8; cn++)
        #pragma unroll
        for (int u = 0; u < 4; u++) O[cn][u] = 0.f;

    for (int jt = 0; jt < NN/64; jt++) {
        const int j0 = jt * 64;
        __syncthreads();
        {
            const __nv_bfloat16* qH = &g_qh[(size_t)(b*NN + j0)*CC];
            const __nv_bfloat16* qL = &g_ql[(size_t)(b*NN + j0)*CC];
            const __nv_bfloat16* vH = &g_vh[(size_t)(b*NN + j0)*CC];
            const __nv_bfloat16* vL = &g_vl[(size_t)(b*NN + j0)*CC];
            for (int idx = t; idx < 512; idx += 256) {
                int row = idx >> 3, seg = idx & 7;
                *(uint4*)(smc + AH_QH + row*BPITCH + seg*16) = *(const uint4*)&qH[row*64 + seg*8];
                *(uint4*)(smc + AH_QL + row*BPITCH + seg*16) = *(const uint4*)&qL[row*64 + seg*8];
                *(uint4*)(smc + AH_VH + row*BPITCH + seg*16) = *(const uint4*)&vH[row*64 + seg*8];
                *(uint4*)(smc + AH_VL + row*BPITCH + seg*16) = *(const uint4*)&vL[row*64 + seg*8];
            }
            if (t < 64) zr[t] = g_zi[b*NN + j0 + t];
        }
        __syncthreads();

        // S^T tile + pack P fragments (A-operand of PV mma)
        uint32_t PAh[4][4], PAl[4][4];
        #pragma unroll
        for (int kp = 0; kp < 4; kp++) {
            #pragma unroll
            for (int half = 0; half < 2; half++) {
                const int nt = kp*2 + half;
                uint32_t bh[8], bl[8];
                ldsm4(addrB(sb + AH_QH, nt*8,  0, lr, g), bh);
                ldsm4(addrB(sb + AH_QH, nt*8, 32, lr, g), bh + 4);
                ldsm4(addrB(sb + AH_QL, nt*8,  0, lr, g), bl);
                ldsm4(addrB(sb + AH_QL, nt*8, 32, lr, g), bl + 4);
                float C[4] = {0.f, 0.f, 0.f, 0.f};
                #pragma unroll
                for (int ks = 0; ks < 4; ks++) mma16816(C, KAh[ks], bh[2*ks], bh[2*ks+1]);
                #pragma unroll
                for (int ks = 0; ks < 4; ks++) mma16816(C, KAh[ks], bl[2*ks], bl[2*ks+1]);
                #pragma unroll
                for (int ks = 0; ks < 4; ks++) mma16816(C, KAl[ks], bh[2*ks], bh[2*ks+1]);
                const int jc = nt*8 + qc*2;
                const float z0 = zr[jc], z1 = zr[jc + 1];
                float p0 = __expf(C[0]) * z0;
                float p1 = __expf(C[1]) * z1;
                float p2 = __expf(C[2]) * z0;
                float p3 = __expf(C[3]) * z1;
                split2(p0, p1, PAh[kp][half*2],   PAl[kp][half*2]);
                split2(p2, p3, PAh[kp][half*2+1], PAl[kp][half*2+1]);
            }
        }

        // O += P * V   (B = V via ldmatrix.trans)
        #pragma unroll
        for (int cn = 0; cn < 8; cn++) {
            uint32_t vh[8], vl[8];
            ldsm4t(addrBt(sb + AH_VH,  0, cn*8, lr, g), vh);
            ldsm4t(addrBt(sb + AH_VH, 32, cn*8, lr, g), vh + 4);
            ldsm4t(addrBt(sb + AH_VL,  0, cn*8, lr, g), vl);
            ldsm4t(addrBt(sb + AH_VL, 32, cn*8, lr, g), vl + 4);
            #pragma unroll
            for (int ks = 0; ks < 4; ks++) mma16816(O[cn], PAh[ks], vh[2*ks], vh[2*ks+1]);
            #pragma unroll
            for (int ks = 0; ks < 4; ks++) mma16816(O[cn], PAh[ks], vl[2*ks], vl[2*ks+1]);
            #pragma unroll
            for (int ks = 0; ks < 4; ks++) mma16816(O[cn], PAl[ks], vh[2*ks], vh[2*ks+1]);
        }
    }

    const int row0 = i0 + w*16 + qr;
    #pragma unroll
    for (int cn = 0; cn < 8; cn++) {
        const int col = cn*8 + qc*2;
        *(float2*)&g_res[(size_t)(b*NN + row0)*CC + col]     = make_float2(O[cn][0], O[cn][1]);
        *(float2*)&g_res[(size_t)(b*NN + row0 + 8)*CC + col] = make_float2(O[cn][2], O[cn][3]);
    }
}

// ------------------------------------------------------------------
// Kernel 4: out = Wo @ res + bo + res, output (B,C,H,W)
// ------------------------------------------------------------------
__global__ void out_kernel(const float* __restrict__ Wo, const float* __restrict__ bo,
                           float* __restrict__ out)
{
    __shared__ float ws[CC*PITCH];
    __shared__ float rst[CC*PITCH];
    const int b  = blockIdx.y;
    const int n0 = blockIdx.x * 64;
    const int t  = threadIdx.x;

    for (int idx = t; idx < CC*CC; idx += 256) {
        int cout = idx >> 6, cin = idx & 63;
        ws[cin*PITCH + cout] = Wo[idx];
    }
    for (int idx = t; idx < 1024; idx += 256) {
        int cg = idx >> 6, n = idx & 63;
        float4 v = LD4(&g_res[(size_t)(b*NN + n0 + n)*CC + 4*cg]);
        rst[(4*cg+0)*PITCH + n] = v.x;
        rst[(4*cg+1)*PITCH + n] = v.y;
        rst[(4*cg+2)*PITCH + n] = v.z;
        rst[(4*cg+3)*PITCH + n] = v.w;
    }
    __syncthreads();

    const int tx = t & 15, ty = t >> 4;
    float acc[4][4];
    #pragma unroll
    for (int k = 0; k < 4; k++)
        #pragma unroll
        for (int j = 0; j < 4; j++) acc[k][j] = 0.f;

    #pragma unroll 4
    for (int ci = 0; ci < CC; ci++) {
        const float4 r4 = LD4(&rst[ci*PITCH + 4*tx]);
        float wv[4];
        #pragma unroll
        for (int k = 0; k < 4; k++) wv[k] = ws[ci*PITCH + ty + 16*k];
        #pragma unroll
        for (int k = 0; k < 4; k++) {
            acc[k][0] = fmaf(wv[k], r4.x, acc[k][0]);
            acc[k][1] = fmaf(wv[k], r4.y, acc[k][1]);
            acc[k][2] = fmaf(wv[k], r4.z, acc[k][2]);
            acc[k][3] = fmaf(wv[k], r4.w, acc[k][3]);
        }
    }

    #pragma unroll
    for (int k = 0; k < 4; k++) {
        int c = ty + 16*k;
        float bvv = bo[c];
        float4 resid = LD4(&rst[c*PITCH + 4*tx]);
        float4 o;
        o.x = acc[k][0] + bvv + resid.x;
        o.y = acc[k][1] + bvv + resid.y;
        o.z = acc[k][2] + bvv + resid.z;
        o.w = acc[k][3] + bvv + resid.w;
        *(float4*)&out[(size_t)(b*CC + c)*NN + n0 + 4*tx] = o;
    }
}

// ------------------------------------------------------------------
extern "C" void kernel_launch(void* const* d_in, const int* in_sizes, int n_in,
                              void* d_out, int out_size)
{
    const float* x  = (const float*)d_in[0];
    const float* Wq = (const float*)d_in[1];
    const float* bq = (const float*)d_in[2];
    const float* Wk = (const float*)d_in[3];
    const float* bk = (const float*)d_in[4];
    const float* Wv = (const float*)d_in[5];
    const float* bv = (const float*)d_in[6];
    const float* Wo = (const float*)d_in[7];
    const float* bo = (const float*)d_in[8];
    float* out = (float*)d_out;

    const int QKV_SMEM = (3*CC*PITCH + CC*64) * 4;
    cudaFuncSetAttribute(qkv_kernel,   cudaFuncAttributeMaxDynamicSharedMemorySize, QKV_SMEM);
    cudaFuncSetAttribute(stats_kernel, cudaFuncAttributeMaxDynamicSharedMemorySize, ST_SMEM);
    cudaFuncSetAttribute(apply_kernel, cudaFuncAttributeMaxDynamicSharedMemorySize, AP_SMEM);

    qkv_kernel<<<dim3(NN/64, BB), 256, QKV_SMEM>>>(x, Wq, bq, Wk, bk, Wv, bv);
    stats_kernel<<<dim3(NN/128, BB), 256, ST_SMEM>>>();
    apply_kernel<<<dim3(NN/128, BB), 256, AP_SMEM>>>();
    out_kernel<<<dim3(NN/64, BB), 256>>>(Wo, bo, out);
}

// round 4
// speedup vs baseline: 3.1845x; 1.0513x over previous
#include <cuda_runtime.h>
#include <cuda_bf16.h>
#include <cstdint>

#define BB 8
#define CC 64
#define NN 4096
#define PITCH 68      // fp32 smem pitch (qkv/out kernels)
#define BPITCH 144    // bf16 tile pitch bytes (64 elems + pad)
#define APITCH 272    // P-tile pitch bytes (128 elems + pad)

// ---------------- scratch ----------------
__device__ __nv_bfloat16 g_qh[BB*NN*CC], g_ql[BB*NN*CC];
__device__ __nv_bfloat16 g_kh[BB*NN*CC], g_kl[BB*NN*CC];
__device__ __nv_bfloat16 g_vh[BB*NN*CC], g_vl[BB*NN*CC];
__device__ __nv_bfloat16 g_vph[BB*NN*CC], g_vpl[BB*NN*CC];   // v' = v * (1/Z_j)
__device__ __nv_bfloat16 g_ph[(size_t)BB*NN*NN];             // P' = exp(S), [b][j][i]
__device__ __nv_bfloat16 g_pl[(size_t)BB*NN*NN];
__device__ float g_res[BB*NN*CC];

#define LD4(p) (*(const float4*)(p))

__device__ __forceinline__ uint32_t smem_to_u32(const void* p) {
    uint32_t a;
    asm("{ .reg .u64 t; cvta.to.shared.u64 t, %1; cvt.u32.u64 %0, t; }" : "=r"(a) : "l"(p));
    return a;
}
__device__ __forceinline__ void ldsm4(uint32_t addr, uint32_t* r) {
    asm volatile("ldmatrix.sync.aligned.m8n8.x4.shared.b16 {%0,%1,%2,%3}, [%4];"
                 : "=r"(r[0]), "=r"(r[1]), "=r"(r[2]), "=r"(r[3]) : "r"(addr));
}
__device__ __forceinline__ void ldsm4t(uint32_t addr, uint32_t* r) {
    asm volatile("ldmatrix.sync.aligned.m8n8.x4.trans.shared.b16 {%0,%1,%2,%3}, [%4];"
                 : "=r"(r[0]), "=r"(r[1]), "=r"(r[2]), "=r"(r[3]) : "r"(addr));
}
__device__ __forceinline__ void mma16816(float* c, const uint32_t* a, uint32_t b0, uint32_t b1) {
    asm volatile("mma.sync.aligned.m16n8k16.row.col.f32.bf16.bf16.f32 "
                 "{%0,%1,%2,%3}, {%4,%5,%6,%7}, {%8,%9}, {%0,%1,%2,%3};"
                 : "+f"(c[0]), "+f"(c[1]), "+f"(c[2]), "+f"(c[3])
                 : "r"(a[0]), "r"(a[1]), "r"(a[2]), "r"(a[3]), "r"(b0), "r"(b1));
}
__device__ __forceinline__ void split2(float p0, float p1, uint32_t& h, uint32_t& l) {
    __nv_bfloat16 h0 = __float2bfloat16_rn(p0), h1 = __float2bfloat16_rn(p1);
    __nv_bfloat16 l0 = __float2bfloat16_rn(p0 - __bfloat162float(h0));
    __nv_bfloat16 l1 = __float2bfloat16_rn(p1 - __bfloat162float(h1));
    h = ((uint32_t)__bfloat16_as_ushort(h1) << 16) | __bfloat16_as_ushort(h0);
    l = ((uint32_t)__bfloat16_as_ushort(l1) << 16) | __bfloat16_as_ushort(l0);
}
__device__ __forceinline__ float bf_lo(uint32_t wv) {
    return __bfloat162float(__ushort_as_bfloat16((unsigned short)(wv & 0xffff)));
}
__device__ __forceinline__ float bf_hi(uint32_t wv) {
    return __bfloat162float(__ushort_as_bfloat16((unsigned short)(wv >> 16)));
}
__device__ __forceinline__ void cp16(uint32_t saddr, const void* gaddr) {
    asm volatile("cp.async.cg.shared.global [%0], [%1], 16;" :: "r"(saddr), "l"(gaddr));
}
#define CP_COMMIT() asm volatile("cp.async.commit_group;" ::: "memory")
#define CP_WAIT0()  asm volatile("cp.async.wait_group 0;" ::: "memory")
#define CP_WAIT1()  asm volatile("cp.async.wait_group 1;" ::: "memory")

// A fragment m16k16 from [m][k] storage (pitch BPITCH)
__device__ __forceinline__ uint32_t addrA(uint32_t base, int r0, int c0, int lr, int g) {
    return base + (uint32_t)(r0 + lr + ((g & 1) << 3)) * BPITCH + ((uint32_t)(c0 + ((g >> 1) << 3)) << 1);
}
// A fragment m16k16 via trans from [k][m] storage (pitch APITCH): m rows = i, k rows = j
__device__ __forceinline__ uint32_t addrAt(uint32_t base, int m0, int k0, int lr, int g) {
    return base + (uint32_t)(k0 + ((g >> 1) << 3) + lr) * APITCH + ((uint32_t)(m0 + ((g & 1) << 3)) << 1);
}
// B fragments from [n][k] storage
__device__ __forceinline__ uint32_t addrB(uint32_t base, int n0, int k0, int lr, int g) {
    return base + (uint32_t)(n0 + lr) * BPITCH + ((uint32_t)(k0 + g * 8) << 1);
}
// B fragments via trans from [k][n] storage
__device__ __forceinline__ uint32_t addrBt(uint32_t base, int k0, int n0, int lr, int g) {
    return base + (uint32_t)(k0 + g * 8 + lr) * BPITCH + ((uint32_t)n0 << 1);
}

// ------------------------------------------------------------------
// Kernel 1: q,k,v = W @ x + b -> bf16 hi/lo planes, layout [b][n][c]
// ------------------------------------------------------------------
__global__ void qkv_kernel(const float* __restrict__ x,
                           const float* __restrict__ Wq, const float* __restrict__ bq,
                           const float* __restrict__ Wk, const float* __restrict__ bk,
                           const float* __restrict__ Wv, const float* __restrict__ bv)
{
    extern __shared__ float smf[];
    float* ws = smf;
    float* xs = smf + 3*CC*PITCH;
    const int b  = blockIdx.y;
    const int n0 = blockIdx.x * 64;
    const int t  = threadIdx.x;

    const float* Wmats[3] = {Wq, Wk, Wv};
    #pragma unroll
    for (int m = 0; m < 3; m++)
        for (int idx = t; idx < CC*CC; idx += 256) {
            int cout = idx >> 6, cin = idx & 63;
            ws[(m*CC + cin)*PITCH + cout] = Wmats[m][idx];
        }
    for (int idx = t; idx < CC*64; idx += 256) {
        int cin = idx >> 6, n = idx & 63;
        xs[cin*64 + n] = x[(size_t)(b*CC + cin)*NN + n0 + n];
    }
    __syncthreads();

    const int tx = t & 15, ty = t >> 4;
    float acc[3][4][4];
    #pragma unroll
    for (int m = 0; m < 3; m++)
        #pragma unroll
        for (int k = 0; k < 4; k++)
            #pragma unroll
            for (int j = 0; j < 4; j++) acc[m][k][j] = 0.f;

    #pragma unroll 4
    for (int ci = 0; ci < CC; ci++) {
        float xv[4];
        #pragma unroll
        for (int k = 0; k < 4; k++) xv[k] = xs[ci*64 + ty + 16*k];
        #pragma unroll
        for (int m = 0; m < 3; m++) {
            const float4 w4 = LD4(&ws[(m*CC + ci)*PITCH + 4*tx]);
            #pragma unroll
            for (int k = 0; k < 4; k++) {
                acc[m][k][0] = fmaf(xv[k], w4.x, acc[m][k][0]);
                acc[m][k][1] = fmaf(xv[k], w4.y, acc[m][k][1]);
                acc[m][k][2] = fmaf(xv[k], w4.z, acc[m][k][2]);
                acc[m][k][3] = fmaf(xv[k], w4.w, acc[m][k][3]);
            }
        }
    }

    const float* biases[3] = {bq, bk, bv};
    __nv_bfloat16* outsH[3] = {g_qh, g_kh, g_vh};
    __nv_bfloat16* outsL[3] = {g_ql, g_kl, g_vl};
    #pragma unroll
    for (int m = 0; m < 3; m++) {
        const float4 bb4 = LD4(&biases[m][4*tx]);
        const float bbv[4] = {bb4.x, bb4.y, bb4.z, bb4.w};
        #pragma unroll
        for (int k = 0; k < 4; k++) {
            int n = n0 + ty + 16*k;
            uint32_t Hp[2], Lp[2];
            #pragma unroll
            for (int jp = 0; jp < 2; jp++) {
                float v0 = acc[m][k][2*jp]   + bbv[2*jp];
                float v1 = acc[m][k][2*jp+1] + bbv[2*jp+1];
                split2(v0, v1, Hp[jp], Lp[jp]);
            }
            size_t idx = (size_t)(b*NN + n)*CC + 4*tx;
            *reinterpret_cast<uint2*>(&outsH[m][idx]) = make_uint2(Hp[0], Hp[1]);
            *reinterpret_cast<uint2*>(&outsL[m][idx]) = make_uint2(Lp[0], Lp[1]);
        }
    }
}

// ------------------------------------------------------------------
// Kernel 2: S row pass: P'=exp(S) hi/lo -> g_ph/g_pl ([b][j][i]),
//           Z_j accumulated; epilogue writes v' = v/Z_j.
// grid (NN/128, BB), 256 thr. smem:
//   [0..36863]      Q tiles hi/lo (later overlaid by P staging hi/lo)
//   [36864..73727]  K ping-pong (KH0,KL0,KH1,KL1 @ 9216 each)
//   [73728..74239]  zi[128]
// ------------------------------------------------------------------
#define ST_K    36864
#define ST_ZI   73728
#define ST_SMEM 74240

__global__ void __launch_bounds__(256) stats_kernel()
{
    extern __shared__ char smc[];
    const uint32_t sb = smem_to_u32(smc);
    float* szi = reinterpret_cast<float*>(smc + ST_ZI);
    const int b = blockIdx.y, j0 = blockIdx.x * 128;
    const int t = threadIdx.x, w = t >> 5, lane = t & 31;
    const int lr = lane & 7, g = lane >> 3, qr = lane >> 2, qc = lane & 3;

    // prefetch K tiles 0,1
    #pragma unroll
    for (int tile = 0; tile < 2; tile++) {
        const uint32_t dH = sb + ST_K + tile*18432, dL = dH + 9216;
        const int i0n = tile * 64;
        #pragma unroll
        for (int p = 0; p < 2; p++) {
            int idx = t + p*256; int row = idx >> 3, seg = idx & 7;
            cp16(dH + row*BPITCH + seg*16, &g_kh[(size_t)(b*NN + i0n + row)*CC + seg*8]);
            cp16(dL + row*BPITCH + seg*16, &g_kl[(size_t)(b*NN + i0n + row)*CC + seg*8]);
        }
        CP_COMMIT();
    }

    {   // Q tiles (plain loads)
        const __nv_bfloat16* sH = &g_qh[(size_t)(b*NN + j0)*CC];
        const __nv_bfloat16* sL = &g_ql[(size_t)(b*NN + j0)*CC];
        for (int idx = t; idx < 1024; idx += 256) {
            int row = idx >> 3, seg = idx & 7;
            *(uint4*)(smc + row*BPITCH + seg*16)         = *(const uint4*)&sH[row*64 + seg*8];
            *(uint4*)(smc + 18432 + row*BPITCH + seg*16) = *(const uint4*)&sL[row*64 + seg*8];
        }
    }
    __syncthreads();

    uint32_t Ah[4][4], Al[4][4];
    #pragma unroll
    for (int ks = 0; ks < 4; ks++) {
        ldsm4(addrA(sb,         w*16, ks*16, lr, g), Ah[ks]);
        ldsm4(addrA(sb + 18432, w*16, ks*16, lr, g), Al[ks]);
    }

    float zacc0 = 0.f, zacc1 = 0.f;

    for (int it = 0; it < NN/64; it++) {
        if (it < NN/64 - 1) CP_WAIT1(); else CP_WAIT0();
        __syncthreads();   // K tile ready; staging free; Q frags loaded (it==0)

        const uint32_t kbH = sb + ST_K + (it & 1)*18432, kbL = kbH + 9216;
        #pragma unroll
        for (int nt = 0; nt < 8; nt++) {
            uint32_t bh[8], bl[8];
            ldsm4(addrB(kbH, nt*8,  0, lr, g), bh);
            ldsm4(addrB(kbH, nt*8, 32, lr, g), bh + 4);
            ldsm4(addrB(kbL, nt*8,  0, lr, g), bl);
            ldsm4(addrB(kbL, nt*8, 32, lr, g), bl + 4);
            float C[4] = {0.f, 0.f, 0.f, 0.f};
            #pragma unroll
            for (int ks = 0; ks < 4; ks++) mma16816(C, Ah[ks], bh[2*ks], bh[2*ks+1]);
            #pragma unroll
            for (int ks = 0; ks < 4; ks++) mma16816(C, Ah[ks], bl[2*ks], bl[2*ks+1]);
            #pragma unroll
            for (int ks = 0; ks < 4; ks++) mma16816(C, Al[ks], bh[2*ks], bh[2*ks+1]);

            float e0 = __expf(C[0]), e1 = __expf(C[1]);
            float e2 = __expf(C[2]), e3 = __expf(C[3]);
            zacc0 += e0 + e1;
            zacc1 += e2 + e3;
            uint32_t h01, l01, h23, l23;
            split2(e0, e1, h01, l01);
            split2(e2, e3, h23, l23);
            // staging [j 0..127][i 0..63], hi@0, lo@18432, pitch 144
            const uint32_t co = (uint32_t)(nt*8 + qc*2) << 1;
            *(uint32_t*)(smc +         (w*16 + qr)*BPITCH + co)     = h01;
            *(uint32_t*)(smc + 18432 + (w*16 + qr)*BPITCH + co)     = l01;
            *(uint32_t*)(smc +         (w*16 + qr + 8)*BPITCH + co) = h23;
            *(uint32_t*)(smc + 18432 + (w*16 + qr + 8)*BPITCH + co) = l23;
        }
        __syncthreads();   // staging complete

        // cooperative store P' tile -> gmem [b][j0+row][it*64 + 8*seg]
        const size_t pbase = ((size_t)b*NN + j0) * NN + it*64;
        #pragma unroll
        for (int p = 0; p < 4; p++) {
            int idx = t + p*256; int row = idx >> 3, seg = idx & 7;
            *(uint4*)&g_ph[pbase + (size_t)row*NN + seg*8] = *(const uint4*)(smc + row*BPITCH + seg*16);
            *(uint4*)&g_pl[pbase + (size_t)row*NN + seg*8] = *(const uint4*)(smc + 18432 + row*BPITCH + seg*16);
        }
        // prefetch K tile it+2 into the buffer just consumed
        if (it + 2 < NN/64) {
            const uint32_t dH = sb + ST_K + (it & 1)*18432, dL = dH + 9216;
            const int i0n = (it + 2) * 64;
            #pragma unroll
            for (int p = 0; p < 2; p++) {
                int idx = t + p*256; int row = idx >> 3, seg = idx & 7;
                cp16(dH + row*BPITCH + seg*16, &g_kh[(size_t)(b*NN + i0n + row)*CC + seg*8]);
                cp16(dL + row*BPITCH + seg*16, &g_kl[(size_t)(b*NN + i0n + row)*CC + seg*8]);
            }
            CP_COMMIT();
        }
        __syncthreads();   // staging reads done before next overwrite
    }

    // zi -> smem; then v' = (vh+vl) * zi, split, store
    zacc0 += __shfl_xor_sync(0xffffffffu, zacc0, 1);
    zacc0 += __shfl_xor_sync(0xffffffffu, zacc0, 2);
    zacc1 += __shfl_xor_sync(0xffffffffu, zacc1, 1);
    zacc1 += __shfl_xor_sync(0xffffffffu, zacc1, 2);
    if (qc == 0) {
        szi[w*16 + qr]     = 1.f / zacc0;
        szi[w*16 + qr + 8] = 1.f / zacc1;
    }
    __syncthreads();

    #pragma unroll
    for (int p = 0; p < 4; p++) {
        int idx = t + p*256; int row = idx >> 3, seg = idx & 7;
        const float z = szi[row];
        const size_t gofs = (size_t)(b*NN + j0 + row)*CC + seg*8;
        uint4 H = *(const uint4*)&g_vh[gofs];
        uint4 L = *(const uint4*)&g_vl[gofs];
        uint32_t hw[4] = {H.x, H.y, H.z, H.w}, lw[4] = {L.x, L.y, L.z, L.w};
        uint32_t oh[4], ol[4];
        #pragma unroll
        for (int u = 0; u < 4; u++) {
            float v0 = (bf_lo(hw[u]) + bf_lo(lw[u])) * z;
            float v1 = (bf_hi(hw[u]) + bf_hi(lw[u])) * z;
            split2(v0, v1, oh[u], ol[u]);
        }
        *(uint4*)&g_vph[gofs] = make_uint4(oh[0], oh[1], oh[2], oh[3]);
        *(uint4*)&g_vpl[gofs] = make_uint4(ol[0], ol[1], ol[2], ol[3]);
    }
}

// ------------------------------------------------------------------
// Kernel 3: O[i,c] = sum_j P'[j,i] * v'[j,c]   (pure pipelined GEMM)
// grid (NN/128, BB), 256 thr. smem: P ping-pong (64x272)x2planes x2buf,
// V' ping-pong (64x144)x2 x2.
// ------------------------------------------------------------------
#define AP_V    69632
#define AP_SMEM 106496

__global__ void __launch_bounds__(256) apply_kernel()
{
    extern __shared__ char smc[];
    const uint32_t sb = smem_to_u32(smc);
    const int b = blockIdx.y, i0 = blockIdx.x * 128;
    const int t = threadIdx.x, w = t >> 5, lane = t & 31;
    const int lr = lane & 7, g = lane >> 3, qr = lane >> 2, qc = lane & 3;

    // prologue: tiles 0, 1
    #pragma unroll
    for (int tile = 0; tile < 2; tile++) {
        const uint32_t pH = sb + tile*34816, pL = pH + 17408;
        const uint32_t vH = sb + AP_V + tile*18432, vL = vH + 9216;
        const int j0 = tile * 64;
        #pragma unroll
        for (int p = 0; p < 4; p++) {
            int idx = t + p*256; int row = idx >> 4, seg = idx & 15;
            const size_t go = ((size_t)b*NN + j0 + row)*NN + i0 + seg*8;
            cp16(pH + row*APITCH + seg*16, &g_ph[go]);
            cp16(pL + row*APITCH + seg*16, &g_pl[go]);
        }
        #pragma unroll
        for (int p = 0; p < 2; p++) {
            int idx = t + p*256; int row = idx >> 3, seg = idx & 7;
            const size_t go = (size_t)(b*NN + j0 + row)*CC + seg*8;
            cp16(vH + row*BPITCH + seg*16, &g_vph[go]);
            cp16(vL + row*BPITCH + seg*16, &g_vpl[go]);
        }
        CP_COMMIT();
    }

    float O[8][4];
    #pragma unroll
    for (int cn = 0; cn < 8; cn++)
        #pragma unroll
        for (int u = 0; u < 4; u++) O[cn][u] = 0.f;

    for (int jt = 0; jt < NN/64; jt++) {
        if (jt < NN/64 - 1) CP_WAIT1(); else CP_WAIT0();
        __syncthreads();

        const uint32_t pH = sb + (jt & 1)*34816, pL = pH + 17408;
        const uint32_t vH = sb + AP_V + (jt & 1)*18432, vL = vH + 9216;

        // A = P'^T fragments (rows i, k = j) via trans loads from [j][i]
        uint32_t PAh[4][4], PAl[4][4];
        #pragma unroll
        for (int ks = 0; ks < 4; ks++) {
            ldsm4t(addrAt(pH, w*16, ks*16, lr, g), PAh[ks]);
            ldsm4t(addrAt(pL, w*16, ks*16, lr, g), PAl[ks]);
        }
        #pragma unroll
        for (int cn = 0; cn < 8; cn++) {
            uint32_t vhh[8], vll[8];
            ldsm4t(addrBt(vH,  0, cn*8, lr, g), vhh);
            ldsm4t(addrBt(vH, 32, cn*8, lr, g), vhh + 4);
            ldsm4t(addrBt(vL,  0, cn*8, lr, g), vll);
            ldsm4t(addrBt(vL, 32, cn*8, lr, g), vll + 4);
            #pragma unroll
            for (int ks = 0; ks < 4; ks++) mma16816(O[cn], PAh[ks], vhh[2*ks], vhh[2*ks+1]);
            #pragma unroll
            for (int ks = 0; ks < 4; ks++) mma16816(O[cn], PAh[ks], vll[2*ks], vll[2*ks+1]);
            #pragma unroll
            for (int ks = 0; ks < 4; ks++) mma16816(O[cn], PAl[ks], vhh[2*ks], vhh[2*ks+1]);
        }
        __syncthreads();   // all reads of buf done

        if (jt + 2 < NN/64) {
            const uint32_t dpH = sb + (jt & 1)*34816, dpL = dpH + 17408;
            const uint32_t dvH = sb + AP_V + (jt & 1)*18432, dvL = dvH + 9216;
            const int j0n = (jt + 2) * 64;
            #pragma unroll
            for (int p = 0; p < 4; p++) {
                int idx = t + p*256; int row = idx >> 4, seg = idx & 15;
                const size_t go = ((size_t)b*NN + j0n + row)*NN + i0 + seg*8;
                cp16(dpH + row*APITCH + seg*16, &g_ph[go]);
                cp16(dpL + row*APITCH + seg*16, &g_pl[go]);
            }
            #pragma unroll
            for (int p = 0; p < 2; p++) {
                int idx = t + p*256; int row = idx >> 3, seg = idx & 7;
                const size_t go = (size_t)(b*NN + j0n + row)*CC + seg*8;
                cp16(dvH + row*BPITCH + seg*16, &g_vph[go]);
                cp16(dvL + row*BPITCH + seg*16, &g_vpl[go]);
            }
            CP_COMMIT();
        }
    }

    const int row0 = i0 + w*16 + qr;
    #pragma unroll
    for (int cn = 0; cn < 8; cn++) {
        const int col = cn*8 + qc*2;
        *(float2*)&g_res[(size_t)(b*NN + row0)*CC + col]     = make_float2(O[cn][0], O[cn][1]);
        *(float2*)&g_res[(size_t)(b*NN + row0 + 8)*CC + col] = make_float2(O[cn][2], O[cn][3]);
    }
}

// ------------------------------------------------------------------
// Kernel 4: out = Wo @ res + bo + res, output (B,C,H,W)
// ------------------------------------------------------------------
__global__ void out_kernel(const float* __restrict__ Wo, const float* __restrict__ bo,
                           float* __restrict__ out)
{
    __shared__ float ws[CC*PITCH];
    __shared__ float rst[CC*PITCH];
    const int b  = blockIdx.y;
    const int n0 = blockIdx.x * 64;
    const int t  = threadIdx.x;

    for (int idx = t; idx < CC*CC; idx += 256) {
        int cout = idx >> 6, cin = idx & 63;
        ws[cin*PITCH + cout] = Wo[idx];
    }
    for (int idx = t; idx < 1024; idx += 256) {
        int cg = idx >> 6, n = idx & 63;
        float4 v = LD4(&g_res[(size_t)(b*NN + n0 + n)*CC + 4*cg]);
        rst[(4*cg+0)*PITCH + n] = v.x;
        rst[(4*cg+1)*PITCH + n] = v.y;
        rst[(4*cg+2)*PITCH + n] = v.z;
        rst[(4*cg+3)*PITCH + n] = v.w;
    }
    __syncthreads();

    const int tx = t & 15, ty = t >> 4;
    float acc[4][4];
    #pragma unroll
    for (int k = 0; k < 4; k++)
        #pragma unroll
        for (int j = 0; j < 4; j++) acc[k][j] = 0.f;

    #pragma unroll 4
    for (int ci = 0; ci < CC; ci++) {
        const float4 r4 = LD4(&rst[ci*PITCH + 4*tx]);
        float wv[4];
        #pragma unroll
        for (int k = 0; k < 4; k++) wv[k] = ws[ci*PITCH + ty + 16*k];
        #pragma unroll
        for (int k = 0; k < 4; k++) {
            acc[k][0] = fmaf(wv[k], r4.x, acc[k][0]);
            acc[k][1] = fmaf(wv[k], r4.y, acc[k][1]);
            acc[k][2] = fmaf(wv[k], r4.z, acc[k][2]);
            acc[k][3] = fmaf(wv[k], r4.w, acc[k][3]);
        }
    }

    #pragma unroll
    for (int k = 0; k < 4; k++) {
        int c = ty + 16*k;
        float bvv = bo[c];
        float4 resid = LD4(&rst[c*PITCH + 4*tx]);
        float4 o;
        o.x = acc[k][0] + bvv + resid.x;
        o.y = acc[k][1] + bvv + resid.y;
        o.z = acc[k][2] + bvv + resid.z;
        o.w = acc[k][3] + bvv + resid.w;
        *(float4*)&out[(size_t)(b*CC + c)*NN + n0 + 4*tx] = o;
    }
}

// ------------------------------------------------------------------
extern "C" void kernel_launch(void* const* d_in, const int* in_sizes, int n_in,
                              void* d_out, int out_size)
{
    const float* x  = (const float*)d_in[0];
    const float* Wq = (const float*)d_in[1];
    const float* bq = (const float*)d_in[2];
    const float* Wk = (const float*)d_in[3];
    const float* bk = (const float*)d_in[4];
    const float* Wv = (const float*)d_in[5];
    const float* bv = (const float*)d_in[6];
    const float* Wo = (const float*)d_in[7];
    const float* bo = (const float*)d_in[8];
    float* out = (float*)d_out;

    const int QKV_SMEM = (3*CC*PITCH + CC*64) * 4;
    cudaFuncSetAttribute(qkv_kernel,   cudaFuncAttributeMaxDynamicSharedMemorySize, QKV_SMEM);
    cudaFuncSetAttribute(stats_kernel, cudaFuncAttributeMaxDynamicSharedMemorySize, ST_SMEM);
    cudaFuncSetAttribute(apply_kernel, cudaFuncAttributeMaxDynamicSharedMemorySize, AP_SMEM);

    qkv_kernel<<<dim3(NN/64, BB), 256, QKV_SMEM>>>(x, Wq, bq, Wk, bk, Wv, bv);
    stats_kernel<<<dim3(NN/128, BB), 256, ST_SMEM>>>();
    apply_kernel<<<dim3(NN/128, BB), 256, AP_SMEM>>>();
    out_kernel<<<dim3(NN/64, BB), 256>>>(Wo, bo, out);
}

// round 5
// speedup vs baseline: 4.2333x; 1.3293x over previous
#include <cuda_runtime.h>
#include <cuda_bf16.h>
#include <cstdint>

#define BB 8
#define CC 64
#define NN 4096
#define PITCH 68      // fp32 smem pitch (qkv/out kernels)
#define BPITCH 144    // bf16 tile pitch bytes (stats Q/K tiles)

// ---------------- scratch ----------------
__device__ __nv_bfloat16 g_qh[BB*NN*CC], g_ql[BB*NN*CC];
__device__ __nv_bfloat16 g_kh[BB*NN*CC], g_kl[BB*NN*CC];
__device__ __nv_bfloat16 g_vh[BB*NN*CC], g_vl[BB*NN*CC];
__device__ uint32_t g_pf[(size_t)BB*NN*NN];   // P' = exp(S), tf32 bits, [b][j][i]
__device__ uint32_t g_vpf[BB*NN*CC];          // v' = v/Z_j, tf32 bits, [b][j][c]
__device__ float g_res[BB*NN*CC];

#define LD4(p) (*(const float4*)(p))

__device__ __forceinline__ uint32_t smem_to_u32(const void* p) {
    uint32_t a;
    asm("{ .reg .u64 t; cvta.to.shared.u64 t, %1; cvt.u32.u64 %0, t; }" : "=r"(a) : "l"(p));
    return a;
}
__device__ __forceinline__ void ldsm4(uint32_t addr, uint32_t* r) {
    asm volatile("ldmatrix.sync.aligned.m8n8.x4.shared.b16 {%0,%1,%2,%3}, [%4];"
                 : "=r"(r[0]), "=r"(r[1]), "=r"(r[2]), "=r"(r[3]) : "r"(addr));
}
__device__ __forceinline__ void mma16816(float* c, const uint32_t* a, uint32_t b0, uint32_t b1) {
    asm volatile("mma.sync.aligned.m16n8k16.row.col.f32.bf16.bf16.f32 "
                 "{%0,%1,%2,%3}, {%4,%5,%6,%7}, {%8,%9}, {%0,%1,%2,%3};"
                 : "+f"(c[0]), "+f"(c[1]), "+f"(c[2]), "+f"(c[3])
                 : "r"(a[0]), "r"(a[1]), "r"(a[2]), "r"(a[3]), "r"(b0), "r"(b1));
}
__device__ __forceinline__ void mma_tf32(float* c, const uint32_t* a, uint32_t b0, uint32_t b1) {
    asm volatile("mma.sync.aligned.m16n8k8.row.col.f32.tf32.tf32.f32 "
                 "{%0,%1,%2,%3}, {%4,%5,%6,%7}, {%8,%9}, {%0,%1,%2,%3};"
                 : "+f"(c[0]), "+f"(c[1]), "+f"(c[2]), "+f"(c[3])
                 : "r"(a[0]), "r"(a[1]), "r"(a[2]), "r"(a[3]), "r"(b0), "r"(b1));
}
__device__ __forceinline__ uint32_t to_tf32(float f) {
    uint32_t r;
    asm("cvt.rna.tf32.f32 %0, %1;" : "=r"(r) : "f"(f));
    return r;
}
__device__ __forceinline__ void split2(float p0, float p1, uint32_t& h, uint32_t& l) {
    __nv_bfloat16 h0 = __float2bfloat16_rn(p0), h1 = __float2bfloat16_rn(p1);
    __nv_bfloat16 l0 = __float2bfloat16_rn(p0 - __bfloat162float(h0));
    __nv_bfloat16 l1 = __float2bfloat16_rn(p1 - __bfloat162float(h1));
    h = ((uint32_t)__bfloat16_as_ushort(h1) << 16) | __bfloat16_as_ushort(h0);
    l = ((uint32_t)__bfloat16_as_ushort(l1) << 16) | __bfloat16_as_ushort(l0);
}
__device__ __forceinline__ float bf_lo(uint32_t wv) {
    return __bfloat162float(__ushort_as_bfloat16((unsigned short)(wv & 0xffff)));
}
__device__ __forceinline__ float bf_hi(uint32_t wv) {
    return __bfloat162float(__ushort_as_bfloat16((unsigned short)(wv >> 16)));
}
__device__ __forceinline__ void cp16(uint32_t saddr, const void* gaddr) {
    asm volatile("cp.async.cg.shared.global [%0], [%1], 16;" :: "r"(saddr), "l"(gaddr));
}
#define CP_COMMIT() asm volatile("cp.async.commit_group;" ::: "memory")
#define CP_WAIT0()  asm volatile("cp.async.wait_group 0;" ::: "memory")
#define CP_WAIT1()  asm volatile("cp.async.wait_group 1;" ::: "memory")

// A fragment m16k16 from [m][k] bf16 storage (pitch BPITCH)
__device__ __forceinline__ uint32_t addrA(uint32_t base, int r0, int c0, int lr, int g) {
    return base + (uint32_t)(r0 + lr + ((g & 1) << 3)) * BPITCH + ((uint32_t)(c0 + ((g >> 1) << 3)) << 1);
}
// B fragments from [n][k] bf16 storage
__device__ __forceinline__ uint32_t addrB(uint32_t base, int n0, int k0, int lr, int g) {
    return base + (uint32_t)(n0 + lr) * BPITCH + ((uint32_t)(k0 + g * 8) << 1);
}

// ------------------------------------------------------------------
// Kernel 1: q,k,v = W @ x + b -> bf16 hi/lo planes, layout [b][n][c]
// ------------------------------------------------------------------
__global__ void qkv_kernel(const float* __restrict__ x,
                           const float* __restrict__ Wq, const float* __restrict__ bq,
                           const float* __restrict__ Wk, const float* __restrict__ bk,
                           const float* __restrict__ Wv, const float* __restrict__ bv)
{
    extern __shared__ float smf[];
    float* ws = smf;
    float* xs = smf + 3*CC*PITCH;
    const int b  = blockIdx.y;
    const int n0 = blockIdx.x * 64;
    const int t  = threadIdx.x;

    const float* Wmats[3] = {Wq, Wk, Wv};
    #pragma unroll
    for (int m = 0; m < 3; m++)
        for (int idx = t; idx < CC*CC; idx += 256) {
            int cout = idx >> 6, cin = idx & 63;
            ws[(m*CC + cin)*PITCH + cout] = Wmats[m][idx];
        }
    for (int idx = t; idx < CC*64; idx += 256) {
        int cin = idx >> 6, n = idx & 63;
        xs[cin*64 + n] = x[(size_t)(b*CC + cin)*NN + n0 + n];
    }
    __syncthreads();

    const int tx = t & 15, ty = t >> 4;
    float acc[3][4][4];
    #pragma unroll
    for (int m = 0; m < 3; m++)
        #pragma unroll
        for (int k = 0; k < 4; k++)
            #pragma unroll
            for (int j = 0; j < 4; j++) acc[m][k][j] = 0.f;

    #pragma unroll 4
    for (int ci = 0; ci < CC; ci++) {
        float xv[4];
        #pragma unroll
        for (int k = 0; k < 4; k++) xv[k] = xs[ci*64 + ty + 16*k];
        #pragma unroll
        for (int m = 0; m < 3; m++) {
            const float4 w4 = LD4(&ws[(m*CC + ci)*PITCH + 4*tx]);
            #pragma unroll
            for (int k = 0; k < 4; k++) {
                acc[m][k][0] = fmaf(xv[k], w4.x, acc[m][k][0]);
                acc[m][k][1] = fmaf(xv[k], w4.y, acc[m][k][1]);
                acc[m][k][2] = fmaf(xv[k], w4.z, acc[m][k][2]);
                acc[m][k][3] = fmaf(xv[k], w4.w, acc[m][k][3]);
            }
        }
    }

    const float* biases[3] = {bq, bk, bv};
    __nv_bfloat16* outsH[3] = {g_qh, g_kh, g_vh};
    __nv_bfloat16* outsL[3] = {g_ql, g_kl, g_vl};
    #pragma unroll
    for (int m = 0; m < 3; m++) {
        const float4 bb4 = LD4(&biases[m][4*tx]);
        const float bbv[4] = {bb4.x, bb4.y, bb4.z, bb4.w};
        #pragma unroll
        for (int k = 0; k < 4; k++) {
            int n = n0 + ty + 16*k;
            uint32_t Hp[2], Lp[2];
            #pragma unroll
            for (int jp = 0; jp < 2; jp++) {
                float v0 = acc[m][k][2*jp]   + bbv[2*jp];
                float v1 = acc[m][k][2*jp+1] + bbv[2*jp+1];
                split2(v0, v1, Hp[jp], Lp[jp]);
            }
            size_t idx = (size_t)(b*NN + n)*CC + 4*tx;
            *reinterpret_cast<uint2*>(&outsH[m][idx]) = make_uint2(Hp[0], Hp[1]);
            *reinterpret_cast<uint2*>(&outsL[m][idx]) = make_uint2(Lp[0], Lp[1]);
        }
    }
}

// ------------------------------------------------------------------
// Kernel 2: stats: S = QK^T (bf16 3-term), P' = exp(S) -> tf32 STG direct,
//           Z accumulated; epilogue v' = v/Z -> tf32.
// grid (NN/128, BB), 256 thr.
// smem: [0..36863] Q hi/lo; [36864..73727] K ping-pong; [73728..74239] zi
// ------------------------------------------------------------------
#define ST_K    36864
#define ST_ZI   73728
#define ST_SMEM 74240

__global__ void __launch_bounds__(256) stats_kernel()
{
    extern __shared__ char smc[];
    const uint32_t sb = smem_to_u32(smc);
    float* szi = reinterpret_cast<float*>(smc + ST_ZI);
    const int b = blockIdx.y, j0 = blockIdx.x * 128;
    const int t = threadIdx.x, w = t >> 5, lane = t & 31;
    const int lr = lane & 7, g = lane >> 3, qr = lane >> 2, qc = lane & 3;

    // prefetch K tiles 0,1
    #pragma unroll
    for (int tile = 0; tile < 2; tile++) {
        const uint32_t dH = sb + ST_K + tile*18432, dL = dH + 9216;
        const int i0n = tile * 64;
        #pragma unroll
        for (int p = 0; p < 2; p++) {
            int idx = t + p*256; int row = idx >> 3, seg = idx & 7;
            cp16(dH + row*BPITCH + seg*16, &g_kh[(size_t)(b*NN + i0n + row)*CC + seg*8]);
            cp16(dL + row*BPITCH + seg*16, &g_kl[(size_t)(b*NN + i0n + row)*CC + seg*8]);
        }
        CP_COMMIT();
    }

    {   // Q tiles (plain loads)
        const __nv_bfloat16* sH = &g_qh[(size_t)(b*NN + j0)*CC];
        const __nv_bfloat16* sL = &g_ql[(size_t)(b*NN + j0)*CC];
        for (int idx = t; idx < 1024; idx += 256) {
            int row = idx >> 3, seg = idx & 7;
            *(uint4*)(smc + row*BPITCH + seg*16)         = *(const uint4*)&sH[row*64 + seg*8];
            *(uint4*)(smc + 18432 + row*BPITCH + seg*16) = *(const uint4*)&sL[row*64 + seg*8];
        }
    }
    __syncthreads();

    uint32_t Ah[4][4], Al[4][4];
    #pragma unroll
    for (int ks = 0; ks < 4; ks++) {
        ldsm4(addrA(sb,         w*16, ks*16, lr, g), Ah[ks]);
        ldsm4(addrA(sb + 18432, w*16, ks*16, lr, g), Al[ks]);
    }

    float zacc0 = 0.f, zacc1 = 0.f;
    const int jlo = j0 + w*16 + qr;

    for (int it = 0; it < NN/64; it++) {
        if (it < NN/64 - 1) CP_WAIT1(); else CP_WAIT0();
        __syncthreads();   // K tile visible to all warps

        const uint32_t kbH = sb + ST_K + (it & 1)*18432, kbL = kbH + 9216;
        #pragma unroll
        for (int nt = 0; nt < 8; nt++) {
            uint32_t bh[8], bl[8];
            ldsm4(addrB(kbH, nt*8,  0, lr, g), bh);
            ldsm4(addrB(kbH, nt*8, 32, lr, g), bh + 4);
            ldsm4(addrB(kbL, nt*8,  0, lr, g), bl);
            ldsm4(addrB(kbL, nt*8, 32, lr, g), bl + 4);
            float C[4] = {0.f, 0.f, 0.f, 0.f};
            #pragma unroll
            for (int ks = 0; ks < 4; ks++) mma16816(C, Ah[ks], bh[2*ks], bh[2*ks+1]);
            #pragma unroll
            for (int ks = 0; ks < 4; ks++) mma16816(C, Ah[ks], bl[2*ks], bl[2*ks+1]);
            #pragma unroll
            for (int ks = 0; ks < 4; ks++) mma16816(C, Al[ks], bh[2*ks], bh[2*ks+1]);

            float e0 = __expf(C[0]), e1 = __expf(C[1]);
            float e2 = __expf(C[2]), e3 = __expf(C[3]);
            zacc0 += e0 + e1;
            zacc1 += e2 + e3;
            // store tf32-rounded P' directly (32B-sector aligned STG.64)
            const int icol = it*64 + nt*8 + qc*2;
            *(uint2*)&g_pf[((size_t)b*NN + jlo)*NN + icol]     = make_uint2(to_tf32(e0), to_tf32(e1));
            *(uint2*)&g_pf[((size_t)b*NN + jlo + 8)*NN + icol] = make_uint2(to_tf32(e2), to_tf32(e3));
        }
        __syncthreads();   // all reads of K buffer done

        if (it + 2 < NN/64) {
            const uint32_t dH = sb + ST_K + (it & 1)*18432, dL = dH + 9216;
            const int i0n = (it + 2) * 64;
            #pragma unroll
            for (int p = 0; p < 2; p++) {
                int idx = t + p*256; int row = idx >> 3, seg = idx & 7;
                cp16(dH + row*BPITCH + seg*16, &g_kh[(size_t)(b*NN + i0n + row)*CC + seg*8]);
                cp16(dL + row*BPITCH + seg*16, &g_kl[(size_t)(b*NN + i0n + row)*CC + seg*8]);
            }
            CP_COMMIT();
        }
    }

    // zi; then v' = (vh+vl) * zi -> tf32
    zacc0 += __shfl_xor_sync(0xffffffffu, zacc0, 1);
    zacc0 += __shfl_xor_sync(0xffffffffu, zacc0, 2);
    zacc1 += __shfl_xor_sync(0xffffffffu, zacc1, 1);
    zacc1 += __shfl_xor_sync(0xffffffffu, zacc1, 2);
    if (qc == 0) {
        szi[w*16 + qr]     = 1.f / zacc0;
        szi[w*16 + qr + 8] = 1.f / zacc1;
    }
    __syncthreads();

    #pragma unroll
    for (int p = 0; p < 8; p++) {
        int idx = t + p*256; int row = idx >> 4, seg = idx & 15;   // 128 rows x 16 segs(4 floats)
        const float z = szi[row];
        const size_t gofs = (size_t)(b*NN + j0 + row)*CC + seg*4;
        uint2 H = *(const uint2*)&g_vh[gofs];
        uint2 L = *(const uint2*)&g_vl[gofs];
        uint32_t o0 = to_tf32((bf_lo(H.x) + bf_lo(L.x)) * z);
        uint32_t o1 = to_tf32((bf_hi(H.x) + bf_hi(L.x)) * z);
        uint32_t o2 = to_tf32((bf_lo(H.y) + bf_lo(L.y)) * z);
        uint32_t o3 = to_tf32((bf_hi(H.y) + bf_hi(L.y)) * z);
        *(uint4*)&g_vpf[gofs] = make_uint4(o0, o1, o2, o3);
    }
}

// ------------------------------------------------------------------
// Kernel 3: O[i,c] = sum_j P'[j,i] * v'[j,c]  -- tf32 GEMM, A from [j][i]
// grid (NN/128, BB), 256 thr.
// smem: P tiles (64 x 544B) x2 @0, V tiles (64 x 288B) x2 @69632
// ------------------------------------------------------------------
#define PJF 136        // P smem pitch in floats (544 B)
#define PVF 72         // V smem pitch in floats (288 B)
#define AP_V    69632
#define AP_SMEM 106496

__global__ void __launch_bounds__(256) apply_kernel()
{
    extern __shared__ char smc[];
    const uint32_t sb = smem_to_u32(smc);
    const int b = blockIdx.y, i0 = blockIdx.x * 128;
    const int t = threadIdx.x, w = t >> 5, lane = t & 31;
    const int qr = lane >> 2, qc = lane & 3;

    // prologue: tiles 0, 1
    #pragma unroll
    for (int tile = 0; tile < 2; tile++) {
        const uint32_t pb = sb + tile*34816;
        const uint32_t vb = sb + AP_V + tile*18432;
        const int j0 = tile * 64;
        #pragma unroll
        for (int p = 0; p < 8; p++) {
            int idx = t + p*256; int row = idx >> 5, seg = idx & 31;
            cp16(pb + row*(PJF*4) + seg*16, &g_pf[((size_t)b*NN + j0 + row)*NN + i0 + seg*4]);
        }
        #pragma unroll
        for (int p = 0; p < 4; p++) {
            int idx = t + p*256; int row = idx >> 4, seg = idx & 15;
            cp16(vb + row*(PVF*4) + seg*16, &g_vpf[(size_t)(b*NN + j0 + row)*CC + seg*4]);
        }
        CP_COMMIT();
    }

    float O[8][4];
    #pragma unroll
    for (int cn = 0; cn < 8; cn++)
        #pragma unroll
        for (int u = 0; u < 4; u++) O[cn][u] = 0.f;

    for (int jt = 0; jt < NN/64; jt++) {
        if (jt < NN/64 - 1) CP_WAIT1(); else CP_WAIT0();
        __syncthreads();

        const float* Pf = (const float*)(smc + (jt & 1)*34816);
        const float* Vf = (const float*)(smc + AP_V + (jt & 1)*18432);

        // A = P^T fragments: A[m=i][k=j], tf32 m16n8k8 layout
        uint32_t A[8][4];
        #pragma unroll
        for (int ks = 0; ks < 8; ks++) {
            const int r0 = ks*8 + qc;
            const int m0 = w*16 + qr;
            A[ks][0] = __float_as_uint(Pf[r0*PJF + m0]);
            A[ks][1] = __float_as_uint(Pf[r0*PJF + m0 + 8]);
            A[ks][2] = __float_as_uint(Pf[(r0 + 4)*PJF + m0]);
            A[ks][3] = __float_as_uint(Pf[(r0 + 4)*PJF + m0 + 8]);
        }
        #pragma unroll
        for (int ks = 0; ks < 8; ks++) {
            const int r0 = ks*8 + qc;
            uint32_t b0[8], b1[8];
            #pragma unroll
            for (int cn = 0; cn < 8; cn++) {
                b0[cn] = __float_as_uint(Vf[r0*PVF + cn*8 + qr]);
                b1[cn] = __float_as_uint(Vf[(r0 + 4)*PVF + cn*8 + qr]);
            }
            #pragma unroll
            for (int cn = 0; cn < 8; cn++)
                mma_tf32(O[cn], A[ks], b0[cn], b1[cn]);
        }
        __syncthreads();   // buffer reads complete

        if (jt + 2 < NN/64) {
            const uint32_t pb = sb + (jt & 1)*34816;
            const uint32_t vb = sb + AP_V + (jt & 1)*18432;
            const int j0n = (jt + 2) * 64;
            #pragma unroll
            for (int p = 0; p < 8; p++) {
                int idx = t + p*256; int row = idx >> 5, seg = idx & 31;
                cp16(pb + row*(PJF*4) + seg*16, &g_pf[((size_t)b*NN + j0n + row)*NN + i0 + seg*4]);
            }
            #pragma unroll
            for (int p = 0; p < 4; p++) {
                int idx = t + p*256; int row = idx >> 4, seg = idx & 15;
                cp16(vb + row*(PVF*4) + seg*16, &g_vpf[(size_t)(b*NN + j0n + row)*CC + seg*4]);
            }
            CP_COMMIT();
        }
    }

    const int row0 = i0 + w*16 + qr;
    #pragma unroll
    for (int cn = 0; cn < 8; cn++) {
        const int col = cn*8 + qc*2;
        *(float2*)&g_res[(size_t)(b*NN + row0)*CC + col]     = make_float2(O[cn][0], O[cn][1]);
        *(float2*)&g_res[(size_t)(b*NN + row0 + 8)*CC + col] = make_float2(O[cn][2], O[cn][3]);
    }
}

// ------------------------------------------------------------------
// Kernel 4: out = Wo @ res + bo + res, output (B,C,H,W)
// ------------------------------------------------------------------
__global__ void out_kernel(const float* __restrict__ Wo, const float* __restrict__ bo,
                           float* __restrict__ out)
{
    __shared__ float ws[CC*PITCH];
    __shared__ float rst[CC*PITCH];
    const int b  = blockIdx.y;
    const int n0 = blockIdx.x * 64;
    const int t  = threadIdx.x;

    for (int idx = t; idx < CC*CC; idx += 256) {
        int cout = idx >> 6, cin = idx & 63;
        ws[cin*PITCH + cout] = Wo[idx];
    }
    for (int idx = t; idx < 1024; idx += 256) {
        int cg = idx >> 6, n = idx & 63;
        float4 v = LD4(&g_res[(size_t)(b*NN + n0 + n)*CC + 4*cg]);
        rst[(4*cg+0)*PITCH + n] = v.x;
        rst[(4*cg+1)*PITCH + n] = v.y;
        rst[(4*cg+2)*PITCH + n] = v.z;
        rst[(4*cg+3)*PITCH + n] = v.w;
    }
    __syncthreads();

    const int tx = t & 15, ty = t >> 4;
    float acc[4][4];
    #pragma unroll
    for (int k = 0; k < 4; k++)
        #pragma unroll
        for (int j = 0; j < 4; j++) acc[k][j] = 0.f;

    #pragma unroll 4
    for (int ci = 0; ci < CC; ci++) {
        const float4 r4 = LD4(&rst[ci*PITCH + 4*tx]);
        float wv[4];
        #pragma unroll
        for (int k = 0; k < 4; k++) wv[k] = ws[ci*PITCH + ty + 16*k];
        #pragma unroll
        for (int k = 0; k < 4; k++) {
            acc[k][0] = fmaf(wv[k], r4.x, acc[k][0]);
            acc[k][1] = fmaf(wv[k], r4.y, acc[k][1]);
            acc[k][2] = fmaf(wv[k], r4.z, acc[k][2]);
            acc[k][3] = fmaf(wv[k], r4.w, acc[k][3]);
        }
    }

    #pragma unroll
    for (int k = 0; k < 4; k++) {
        int c = ty + 16*k;
        float bvv = bo[c];
        float4 resid = LD4(&rst[c*PITCH + 4*tx]);
        float4 o;
        o.x = acc[k][0] + bvv + resid.x;
        o.y = acc[k][1] + bvv + resid.y;
        o.z = acc[k][2] + bvv + resid.z;
        o.w = acc[k][3] + bvv + resid.w;
        *(float4*)&out[(size_t)(b*CC + c)*NN + n0 + 4*tx] = o;
    }
}

// ------------------------------------------------------------------
extern "C" void kernel_launch(void* const* d_in, const int* in_sizes, int n_in,
                              void* d_out, int out_size)
{
    const float* x  = (const float*)d_in[0];
    const float* Wq = (const float*)d_in[1];
    const float* bq = (const float*)d_in[2];
    const float* Wk = (const float*)d_in[3];
    const float* bk = (const float*)d_in[4];
    const float* Wv = (const float*)d_in[5];
    const float* bv = (const float*)d_in[6];
    const float* Wo = (const float*)d_in[7];
    const float* bo = (const float*)d_in[8];
    float* out = (float*)d_out;

    const int QKV_SMEM = (3*CC*PITCH + CC*64) * 4;
    cudaFuncSetAttribute(qkv_kernel,   cudaFuncAttributeMaxDynamicSharedMemorySize, QKV_SMEM);
    cudaFuncSetAttribute(stats_kernel, cudaFuncAttributeMaxDynamicSharedMemorySize, ST_SMEM);
    cudaFuncSetAttribute(apply_kernel, cudaFuncAttributeMaxDynamicSharedMemorySize, AP_SMEM);

    qkv_kernel<<<dim3(NN/64, BB), 256, QKV_SMEM>>>(x, Wq, bq, Wk, bk, Wv, bv);
    stats_kernel<<<dim3(NN/128, BB), 256, ST_SMEM>>>();
    apply_kernel<<<dim3(NN/128, BB), 256, AP_SMEM>>>();
    out_kernel<<<dim3(NN/64, BB), 256>>>(Wo, bo, out);
}

// round 6
// speedup vs baseline: 4.7760x; 1.1282x over previous
#include <cuda_runtime.h>
#include <cuda_bf16.h>
#include <cuda_fp16.h>
#include <cstdint>

#define BB 8
#define CC 64
#define NN 4096
#define PITCH 68      // fp32 smem pitch (qkv/out kernels)
#define BPITCH 144    // bf16 tile pitch bytes (stats Q/K tiles)
#define APITCH 272    // apply P-tile pitch bytes (128 fp16 + pad)

// ---------------- scratch ----------------
__device__ __nv_bfloat16 g_qh[BB*NN*CC], g_ql[BB*NN*CC];
__device__ __nv_bfloat16 g_kh[BB*NN*CC], g_kl[BB*NN*CC];
__device__ __half g_vf[BB*NN*CC];                   // V fp16 [b][j][c]
__device__ __half g_pf16[(size_t)BB*NN*NN];         // P~ = exp(s - m_t), fp16, [b][j][i-permuted]
__device__ float  g_em[(size_t)BB*64*NN];           // e^{m_t(j)}  [b][t][j]
__device__ __half g_azh[(size_t)BB*64*NN];          // az = e^{m_t}/Z_j fp16 [b][t][j]
__device__ float  g_zi[BB*NN];
__device__ float  g_res[BB*NN*CC];

#define LD4(p) (*(const float4*)(p))

__device__ __forceinline__ uint32_t smem_to_u32(const void* p) {
    uint32_t a;
    asm("{ .reg .u64 t; cvta.to.shared.u64 t, %1; cvt.u32.u64 %0, t; }" : "=r"(a) : "l"(p));
    return a;
}
__device__ __forceinline__ void ldsm4(uint32_t addr, uint32_t* r) {
    asm volatile("ldmatrix.sync.aligned.m8n8.x4.shared.b16 {%0,%1,%2,%3}, [%4];"
                 : "=r"(r[0]), "=r"(r[1]), "=r"(r[2]), "=r"(r[3]) : "r"(addr));
}
__device__ __forceinline__ void ldsm4t(uint32_t addr, uint32_t* r) {
    asm volatile("ldmatrix.sync.aligned.m8n8.x4.trans.shared.b16 {%0,%1,%2,%3}, [%4];"
                 : "=r"(r[0]), "=r"(r[1]), "=r"(r[2]), "=r"(r[3]) : "r"(addr));
}
__device__ __forceinline__ void mma16816(float* c, const uint32_t* a, uint32_t b0, uint32_t b1) {
    asm volatile("mma.sync.aligned.m16n8k16.row.col.f32.bf16.bf16.f32 "
                 "{%0,%1,%2,%3}, {%4,%5,%6,%7}, {%8,%9}, {%0,%1,%2,%3};"
                 : "+f"(c[0]), "+f"(c[1]), "+f"(c[2]), "+f"(c[3])
                 : "r"(a[0]), "r"(a[1]), "r"(a[2]), "r"(a[3]), "r"(b0), "r"(b1));
}
__device__ __forceinline__ void mma16816h(float* c, const uint32_t* a, uint32_t b0, uint32_t b1) {
    asm volatile("mma.sync.aligned.m16n8k16.row.col.f32.f16.f16.f32 "
                 "{%0,%1,%2,%3}, {%4,%5,%6,%7}, {%8,%9}, {%0,%1,%2,%3};"
                 : "+f"(c[0]), "+f"(c[1]), "+f"(c[2]), "+f"(c[3])
                 : "r"(a[0]), "r"(a[1]), "r"(a[2]), "r"(a[3]), "r"(b0), "r"(b1));
}
__device__ __forceinline__ uint32_t packh2(float lo, float hi) {
    __half2 h = __floats2half2_rn(lo, hi);
    return *reinterpret_cast<uint32_t*>(&h);
}
__device__ __forceinline__ uint32_t hmul2u(uint32_t a, uint32_t b) {
    __half2 r = __hmul2(*reinterpret_cast<__half2*>(&a), *reinterpret_cast<__half2*>(&b));
    return *reinterpret_cast<uint32_t*>(&r);
}
__device__ __forceinline__ void split2(float p0, float p1, uint32_t& h, uint32_t& l) {
    __nv_bfloat16 h0 = __float2bfloat16_rn(p0), h1 = __float2bfloat16_rn(p1);
    __nv_bfloat16 l0 = __float2bfloat16_rn(p0 - __bfloat162float(h0));
    __nv_bfloat16 l1 = __float2bfloat16_rn(p1 - __bfloat162float(h1));
    h = ((uint32_t)__bfloat16_as_ushort(h1) << 16) | __bfloat16_as_ushort(h0);
    l = ((uint32_t)__bfloat16_as_ushort(l1) << 16) | __bfloat16_as_ushort(l0);
}
__device__ __forceinline__ void cp16(uint32_t saddr, const void* gaddr) {
    asm volatile("cp.async.cg.shared.global [%0], [%1], 16;" :: "r"(saddr), "l"(gaddr));
}
#define CP_COMMIT() asm volatile("cp.async.commit_group;" ::: "memory")
#define CP_WAIT0()  asm volatile("cp.async.wait_group 0;" ::: "memory")
#define CP_WAIT1()  asm volatile("cp.async.wait_group 1;" ::: "memory")

// A fragment m16k16 from [m][k] bf16 storage (pitch BPITCH)
__device__ __forceinline__ uint32_t addrA(uint32_t base, int r0, int c0, int lr, int g) {
    return base + (uint32_t)(r0 + lr + ((g & 1) << 3)) * BPITCH + ((uint32_t)(c0 + ((g >> 1) << 3)) << 1);
}
// B fragments from [n][k] bf16 storage
__device__ __forceinline__ uint32_t addrB(uint32_t base, int n0, int k0, int lr, int g) {
    return base + (uint32_t)(n0 + lr) * BPITCH + ((uint32_t)(k0 + g * 8) << 1);
}
// A fragment m16k16 via trans from [k][m] fp16 storage (pitch APITCH)
__device__ __forceinline__ uint32_t addrAt(uint32_t base, int m0, int k0, int lr, int g) {
    return base + (uint32_t)(k0 + ((g >> 1) << 3) + lr) * APITCH + ((uint32_t)(m0 + ((g & 1) << 3)) << 1);
}
// B fragments via trans from [k][n] fp16 storage (pitch BPITCH)
__device__ __forceinline__ uint32_t addrBt(uint32_t base, int k0, int n0, int lr, int g) {
    return base + (uint32_t)(k0 + g * 8 + lr) * BPITCH + ((uint32_t)n0 << 1);
}
// permutation: swap bits [4:3] <-> [2:1] (i within 64-tile)
__device__ __forceinline__ int swapbits(int idx) {
    return (idx & 0x61) | ((idx & 0x18) >> 2) | ((idx & 0x06) << 2);
}

// ------------------------------------------------------------------
// Kernel 1: q,k -> bf16 hi/lo planes [b][n][c]; v -> fp16 [b][n][c]
// ------------------------------------------------------------------
__global__ void qkv_kernel(const float* __restrict__ x,
                           const float* __restrict__ Wq, const float* __restrict__ bq,
                           const float* __restrict__ Wk, const float* __restrict__ bk,
                           const float* __restrict__ Wv, const float* __restrict__ bv)
{
    extern __shared__ float smf[];
    float* ws = smf;
    float* xs = smf + 3*CC*PITCH;
    const int b  = blockIdx.y;
    const int n0 = blockIdx.x * 64;
    const int t  = threadIdx.x;

    const float* Wmats[3] = {Wq, Wk, Wv};
    #pragma unroll
    for (int m = 0; m < 3; m++)
        for (int idx = t; idx < CC*CC; idx += 256) {
            int cout = idx >> 6, cin = idx & 63;
            ws[(m*CC + cin)*PITCH + cout] = Wmats[m][idx];
        }
    for (int idx = t; idx < CC*64; idx += 256) {
        int cin = idx >> 6, n = idx & 63;
        xs[cin*64 + n] = x[(size_t)(b*CC + cin)*NN + n0 + n];
    }
    __syncthreads();

    const int tx = t & 15, ty = t >> 4;
    float acc[3][4][4];
    #pragma unroll
    for (int m = 0; m < 3; m++)
        #pragma unroll
        for (int k = 0; k < 4; k++)
            #pragma unroll
            for (int j = 0; j < 4; j++) acc[m][k][j] = 0.f;

    #pragma unroll 4
    for (int ci = 0; ci < CC; ci++) {
        float xv[4];
        #pragma unroll
        for (int k = 0; k < 4; k++) xv[k] = xs[ci*64 + ty + 16*k];
        #pragma unroll
        for (int m = 0; m < 3; m++) {
            const float4 w4 = LD4(&ws[(m*CC + ci)*PITCH + 4*tx]);
            #pragma unroll
            for (int k = 0; k < 4; k++) {
                acc[m][k][0] = fmaf(xv[k], w4.x, acc[m][k][0]);
                acc[m][k][1] = fmaf(xv[k], w4.y, acc[m][k][1]);
                acc[m][k][2] = fmaf(xv[k], w4.z, acc[m][k][2]);
                acc[m][k][3] = fmaf(xv[k], w4.w, acc[m][k][3]);
            }
        }
    }

    // q, k: bf16 hi/lo
    const float* biases[2] = {bq, bk};
    __nv_bfloat16* outsH[2] = {g_qh, g_kh};
    __nv_bfloat16* outsL[2] = {g_ql, g_kl};
    #pragma unroll
    for (int m = 0; m < 2; m++) {
        const float4 bb4 = LD4(&biases[m][4*tx]);
        const float bbv[4] = {bb4.x, bb4.y, bb4.z, bb4.w};
        #pragma unroll
        for (int k = 0; k < 4; k++) {
            int n = n0 + ty + 16*k;
            uint32_t Hp[2], Lp[2];
            #pragma unroll
            for (int jp = 0; jp < 2; jp++) {
                float v0 = acc[m][k][2*jp]   + bbv[2*jp];
                float v1 = acc[m][k][2*jp+1] + bbv[2*jp+1];
                split2(v0, v1, Hp[jp], Lp[jp]);
            }
            size_t idx = (size_t)(b*NN + n)*CC + 4*tx;
            *reinterpret_cast<uint2*>(&outsH[m][idx]) = make_uint2(Hp[0], Hp[1]);
            *reinterpret_cast<uint2*>(&outsL[m][idx]) = make_uint2(Lp[0], Lp[1]);
        }
    }
    // v: fp16 single
    {
        const float4 bb4 = LD4(&bv[4*tx]);
        #pragma unroll
        for (int k = 0; k < 4; k++) {
            int n = n0 + ty + 16*k;
            uint32_t u0 = packh2(acc[2][k][0] + bb4.x, acc[2][k][1] + bb4.y);
            uint32_t u1 = packh2(acc[2][k][2] + bb4.z, acc[2][k][3] + bb4.w);
            *reinterpret_cast<uint2*>(&g_vf[(size_t)(b*NN + n)*CC + 4*tx]) = make_uint2(u0, u1);
        }
    }
}

// ------------------------------------------------------------------
// Kernel 2: stats: S = QK^T (bf16 3-term); per (j, 64-i tile): m = rowmax,
//           P~ = exp(s-m) fp16 (permuted-i layout, coalesced STG.128),
//           em = e^m; Z accumulated; epilogue az = em/Z fp16.
// grid (NN/128, BB), 256 thr.
// ------------------------------------------------------------------
#define ST_K    36864
#define ST_ZI   73728
#define ST_SMEM 74240

__global__ void __launch_bounds__(256) stats_kernel()
{
    extern __shared__ char smc[];
    const uint32_t sb = smem_to_u32(smc);
    float* szi = reinterpret_cast<float*>(smc + ST_ZI);
    const int b = blockIdx.y, j0 = blockIdx.x * 128;
    const int t = threadIdx.x, w = t >> 5, lane = t & 31;
    const int lr = lane & 7, g = lane >> 3, qr = lane >> 2, qc = lane & 3;

    // prefetch K tiles 0,1
    #pragma unroll
    for (int tile = 0; tile < 2; tile++) {
        const uint32_t dH = sb + ST_K + tile*18432, dL = dH + 9216;
        const int i0n = tile * 64;
        #pragma unroll
        for (int p = 0; p < 2; p++) {
            int idx = t + p*256; int row = idx >> 3, seg = idx & 7;
            cp16(dH + row*BPITCH + seg*16, &g_kh[(size_t)(b*NN + i0n + row)*CC + seg*8]);
            cp16(dL + row*BPITCH + seg*16, &g_kl[(size_t)(b*NN + i0n + row)*CC + seg*8]);
        }
        CP_COMMIT();
    }

    {   // Q tiles (plain loads)
        const __nv_bfloat16* sH = &g_qh[(size_t)(b*NN + j0)*CC];
        const __nv_bfloat16* sL = &g_ql[(size_t)(b*NN + j0)*CC];
        for (int idx = t; idx < 1024; idx += 256) {
            int row = idx >> 3, seg = idx & 7;
            *(uint4*)(smc + row*BPITCH + seg*16)         = *(const uint4*)&sH[row*64 + seg*8];
            *(uint4*)(smc + 18432 + row*BPITCH + seg*16) = *(const uint4*)&sL[row*64 + seg*8];
        }
    }
    __syncthreads();

    uint32_t Ah[4][4], Al[4][4];
    #pragma unroll
    for (int ks = 0; ks < 4; ks++) {
        ldsm4(addrA(sb,         w*16, ks*16, lr, g), Ah[ks]);
        ldsm4(addrA(sb + 18432, w*16, ks*16, lr, g), Al[ks]);
    }

    float zacc0 = 0.f, zacc1 = 0.f;
    const int jlo = j0 + w*16 + qr;   // this lane's first j row

    for (int it = 0; it < NN/64; it++) {
        if (it < NN/64 - 1) CP_WAIT1(); else CP_WAIT0();
        __syncthreads();

        const uint32_t kbH = sb + ST_K + (it & 1)*18432, kbL = kbH + 9216;
        float C[8][4];
        #pragma unroll
        for (int nt = 0; nt < 8; nt++) {
            uint32_t bh[8], bl[8];
            ldsm4(addrB(kbH, nt*8,  0, lr, g), bh);
            ldsm4(addrB(kbH, nt*8, 32, lr, g), bh + 4);
            ldsm4(addrB(kbL, nt*8,  0, lr, g), bl);
            ldsm4(addrB(kbL, nt*8, 32, lr, g), bl + 4);
            C[nt][0] = C[nt][1] = C[nt][2] = C[nt][3] = 0.f;
            #pragma unroll
            for (int ks = 0; ks < 4; ks++) mma16816(C[nt], Ah[ks], bh[2*ks], bh[2*ks+1]);
            #pragma unroll
            for (int ks = 0; ks < 4; ks++) mma16816(C[nt], Ah[ks], bl[2*ks], bl[2*ks+1]);
            #pragma unroll
            for (int ks = 0; ks < 4; ks++) mma16816(C[nt], Al[ks], bh[2*ks], bh[2*ks+1]);
        }

        // per-row tile max (rows qr and qr+8), reduce over qc lanes
        float pm0 = C[0][0], pm1 = C[0][2];
        #pragma unroll
        for (int nt = 0; nt < 8; nt++) {
            pm0 = fmaxf(pm0, fmaxf(C[nt][0], C[nt][1]));
            pm1 = fmaxf(pm1, fmaxf(C[nt][2], C[nt][3]));
        }
        pm0 = fmaxf(pm0, __shfl_xor_sync(0xffffffffu, pm0, 1));
        pm0 = fmaxf(pm0, __shfl_xor_sync(0xffffffffu, pm0, 2));
        pm1 = fmaxf(pm1, __shfl_xor_sync(0xffffffffu, pm1, 1));
        pm1 = fmaxf(pm1, __shfl_xor_sync(0xffffffffu, pm1, 2));
        const float em0 = __expf(pm0), em1 = __expf(pm1);

        float ps0 = 0.f, ps1 = 0.f;
        #pragma unroll
        for (int nt = 0; nt < 8; nt++) {
            C[nt][0] = __expf(C[nt][0] - pm0);
            C[nt][1] = __expf(C[nt][1] - pm0);
            C[nt][2] = __expf(C[nt][2] - pm1);
            C[nt][3] = __expf(C[nt][3] - pm1);
            ps0 += C[nt][0] + C[nt][1];
            ps1 += C[nt][2] + C[nt][3];
        }
        ps0 += __shfl_xor_sync(0xffffffffu, ps0, 1);
        ps0 += __shfl_xor_sync(0xffffffffu, ps0, 2);
        ps1 += __shfl_xor_sync(0xffffffffu, ps1, 1);
        ps1 += __shfl_xor_sync(0xffffffffu, ps1, 2);
        zacc0 += em0 * ps0;
        zacc1 += em1 * ps1;

        // coalesced permuted store: lane owns 8 i per row per pack
        const size_t rb0 = (size_t)(b*NN + jlo)*NN + it*64;
        const size_t rb1 = rb0 + (size_t)8*NN;
        #pragma unroll
        for (int pk = 0; pk < 2; pk++) {
            uint4 u0, u1;
            u0.x = packh2(C[pk*4+0][0], C[pk*4+0][1]);
            u0.y = packh2(C[pk*4+1][0], C[pk*4+1][1]);
            u0.z = packh2(C[pk*4+2][0], C[pk*4+2][1]);
            u0.w = packh2(C[pk*4+3][0], C[pk*4+3][1]);
            u1.x = packh2(C[pk*4+0][2], C[pk*4+0][3]);
            u1.y = packh2(C[pk*4+1][2], C[pk*4+1][3]);
            u1.z = packh2(C[pk*4+2][2], C[pk*4+2][3]);
            u1.w = packh2(C[pk*4+3][2], C[pk*4+3][3]);
            *(uint4*)&g_pf16[rb0 + pk*32 + qc*8] = u0;
            *(uint4*)&g_pf16[rb1 + pk*32 + qc*8] = u1;
        }
        if (qc == 0) {
            g_em[(size_t)(b*64 + it)*NN + jlo]     = em0;
            g_em[(size_t)(b*64 + it)*NN + jlo + 8] = em1;
        }
        __syncthreads();

        if (it + 2 < NN/64) {
            const uint32_t dH = sb + ST_K + (it & 1)*18432, dL = dH + 9216;
            const int i0n = (it + 2) * 64;
            #pragma unroll
            for (int p = 0; p < 2; p++) {
                int idx = t + p*256; int row = idx >> 3, seg = idx & 7;
                cp16(dH + row*BPITCH + seg*16, &g_kh[(size_t)(b*NN + i0n + row)*CC + seg*8]);
                cp16(dL + row*BPITCH + seg*16, &g_kl[(size_t)(b*NN + i0n + row)*CC + seg*8]);
            }
            CP_COMMIT();
        }
    }

    // zacc is fully reduced (replicated across qc lanes)
    if (qc == 0) {
        g_zi[b*NN + jlo]     = 1.f / zacc0;
        g_zi[b*NN + jlo + 8] = 1.f / zacc1;
        szi[w*16 + qr]       = 1.f / zacc0;
        szi[w*16 + qr + 8]   = 1.f / zacc1;
    }
    __syncthreads();

    // az epilogue: az[t][j] = em * zi  (fp16)
    const int jl = t & 127;
    const float zil = szi[jl];
    #pragma unroll 4
    for (int p2 = 0; p2 < 32; p2++) {
        int tt = p2*2 + (t >> 7);
        size_t o = (size_t)(b*64 + tt)*NN + j0 + jl;
        g_azh[o] = __float2half_rn(g_em[o] * zil);
    }
}

// ------------------------------------------------------------------
// Kernel 3: O[i,c] = sum_j (P~[j,i]*az[j,t]) * v[j,c]  -- fp16 GEMM
// grid (NN/128, BB), 256 thr.
// smem: P tiles (64 x 272B) x2 @0, V tiles (64 x 144B) x2 @34816, az @53248
// ------------------------------------------------------------------
#define AP_V    34816
#define AP_AZ   53248
#define AP_SMEM 53760

__global__ void __launch_bounds__(256) apply_kernel()
{
    extern __shared__ char smc[];
    const uint32_t sb = smem_to_u32(smc);
    const int b = blockIdx.y, i0 = blockIdx.x * 128;
    const int t = threadIdx.x, w = t >> 5, lane = t & 31;
    const int lr = lane & 7, g = lane >> 3, qr = lane >> 2, qc = lane & 3;
    const int t0 = blockIdx.x * 2;   // stats tile index of first 64-i half

    // prologue: tiles 0, 1
    #pragma unroll
    for (int tile = 0; tile < 2; tile++) {
        const uint32_t pb = sb + tile*17408;
        const uint32_t vb = sb + AP_V + tile*9216;
        const uint32_t ab = sb + AP_AZ + tile*256;
        const int j0 = tile * 64;
        #pragma unroll
        for (int p = 0; p < 4; p++) {
            int idx = t + p*256; int row = idx >> 4, seg = idx & 15;
            cp16(pb + row*APITCH + seg*16, &g_pf16[((size_t)b*NN + j0 + row)*NN + i0 + seg*8]);
        }
        #pragma unroll
        for (int p = 0; p < 2; p++) {
            int idx = t + p*256; int row = idx >> 3, seg = idx & 7;
            cp16(vb + row*BPITCH + seg*16, &g_vf[(size_t)(b*NN + j0 + row)*CC + seg*8]);
        }
        if (t < 16)
            cp16(ab + t*16, &g_azh[(size_t)(b*64 + t0 + (t >> 3))*NN + j0 + (t & 7)*8]);
        CP_COMMIT();
    }

    float O[8][4];
    #pragma unroll
    for (int cn = 0; cn < 8; cn++)
        #pragma unroll
        for (int u = 0; u < 4; u++) O[cn][u] = 0.f;

    for (int jt = 0; jt < NN/64; jt++) {
        if (jt < NN/64 - 1) CP_WAIT1(); else CP_WAIT0();
        __syncthreads();

        const uint32_t pb = sb + (jt & 1)*17408;
        const uint32_t vb = sb + AP_V + (jt & 1)*9216;
        const char* azp = smc + AP_AZ + (jt & 1)*256 + (w >> 2)*128;

        // A = P~^T frags (m=i', k=j), then scale by az (per 2-j pair)
        uint32_t A[4][4];
        #pragma unroll
        for (int ks = 0; ks < 4; ks++) {
            ldsm4t(addrAt(pb, w*16, ks*16, lr, g), A[ks]);
            uint32_t az01 = *(const uint32_t*)(azp + (ks*16 + 2*qc)*2);
            uint32_t az89 = *(const uint32_t*)(azp + (ks*16 + 2*qc + 8)*2);
            A[ks][0] = hmul2u(A[ks][0], az01);
            A[ks][1] = hmul2u(A[ks][1], az01);
            A[ks][2] = hmul2u(A[ks][2], az89);
            A[ks][3] = hmul2u(A[ks][3], az89);
        }
        #pragma unroll
        for (int cn = 0; cn < 8; cn++) {
            uint32_t vv[8];
            ldsm4t(addrBt(vb,  0, cn*8, lr, g), vv);
            ldsm4t(addrBt(vb, 32, cn*8, lr, g), vv + 4);
            #pragma unroll
            for (int ks = 0; ks < 4; ks++) mma16816h(O[cn], A[ks], vv[2*ks], vv[2*ks+1]);
        }
        __syncthreads();

        if (jt + 2 < NN/64) {
            const uint32_t dpb = sb + (jt & 1)*17408;
            const uint32_t dvb = sb + AP_V + (jt & 1)*9216;
            const uint32_t dab = sb + AP_AZ + (jt & 1)*256;
            const int j0n = (jt + 2) * 64;
            #pragma unroll
            for (int p = 0; p < 4; p++) {
                int idx = t + p*256; int row = idx >> 4, seg = idx & 15;
                cp16(dpb + row*APITCH + seg*16, &g_pf16[((size_t)b*NN + j0n + row)*NN + i0 + seg*8]);
            }
            #pragma unroll
            for (int p = 0; p < 2; p++) {
                int idx = t + p*256; int row = idx >> 3, seg = idx & 7;
                cp16(dvb + row*BPITCH + seg*16, &g_vf[(size_t)(b*NN + j0n + row)*CC + seg*8]);
            }
            if (t < 16)
                cp16(dab + t*16, &g_azh[(size_t)(b*64 + t0 + (t >> 3))*NN + j0n + (t & 7)*8]);
            CP_COMMIT();
        }
    }

    // epilogue: un-permute i' -> i
    const int ia0 = swapbits(w*16 + qr);
    const int ia1 = swapbits(w*16 + qr + 8);
    #pragma unroll
    for (int cn = 0; cn < 8; cn++) {
        const int col = cn*8 + qc*2;
        *(float2*)&g_res[(size_t)(b*NN + i0 + ia0)*CC + col] = make_float2(O[cn][0], O[cn][1]);
        *(float2*)&g_res[(size_t)(b*NN + i0 + ia1)*CC + col] = make_float2(O[cn][2], O[cn][3]);
    }
}

// ------------------------------------------------------------------
// Kernel 4: out = Wo @ res + bo + res, output (B,C,H,W)
// ------------------------------------------------------------------
__global__ void out_kernel(const float* __restrict__ Wo, const float* __restrict__ bo,
                           float* __restrict__ out)
{
    __shared__ float ws[CC*PITCH];
    __shared__ float rst[CC*PITCH];
    const int b  = blockIdx.y;
    const int n0 = blockIdx.x * 64;
    const int t  = threadIdx.x;

    for (int idx = t; idx < CC*CC; idx += 256) {
        int cout = idx >> 6, cin = idx & 63;
        ws[cin*PITCH + cout] = Wo[idx];
    }
    for (int idx = t; idx < 1024; idx += 256) {
        int cg = idx >> 6, n = idx & 63;
        float4 v = LD4(&g_res[(size_t)(b*NN + n0 + n)*CC + 4*cg]);
        rst[(4*cg+0)*PITCH + n] = v.x;
        rst[(4*cg+1)*PITCH + n] = v.y;
        rst[(4*cg+2)*PITCH + n] = v.z;
        rst[(4*cg+3)*PITCH + n] = v.w;
    }
    __syncthreads();

    const int tx = t & 15, ty = t >> 4;
    float acc[4][4];
    #pragma unroll
    for (int k = 0; k < 4; k++)
        #pragma unroll
        for (int j = 0; j < 4; j++) acc[k][j] = 0.f;

    #pragma unroll 4
    for (int ci = 0; ci < CC; ci++) {
        const float4 r4 = LD4(&rst[ci*PITCH + 4*tx]);
        float wv[4];
        #pragma unroll
        for (int k = 0; k < 4; k++) wv[k] = ws[ci*PITCH + ty + 16*k];
        #pragma unroll
        for (int k = 0; k < 4; k++) {
            acc[k][0] = fmaf(wv[k], r4.x, acc[k][0]);
            acc[k][1] = fmaf(wv[k], r4.y, acc[k][1]);
            acc[k][2] = fmaf(wv[k], r4.z, acc[k][2]);
            acc[k][3] = fmaf(wv[k], r4.w, acc[k][3]);
        }
    }

    #pragma unroll
    for (int k = 0; k < 4; k++) {
        int c = ty + 16*k;
        float bvv = bo[c];
        float4 resid = LD4(&rst[c*PITCH + 4*tx]);
        float4 o;
        o.x = acc[k][0] + bvv + resid.x;
        o.y = acc[k][1] + bvv + resid.y;
        o.z = acc[k][2] + bvv + resid.z;
        o.w = acc[k][3] + bvv + resid.w;
        *(float4*)&out[(size_t)(b*CC + c)*NN + n0 + 4*tx] = o;
    }
}

// ------------------------------------------------------------------
extern "C" void kernel_launch(void* const* d_in, const int* in_sizes, int n_in,
                              void* d_out, int out_size)
{
    const float* x  = (const float*)d_in[0];
    const float* Wq = (const float*)d_in[1];
    const float* bq = (const float*)d_in[2];
    const float* Wk = (const float*)d_in[3];
    const float* bk = (const float*)d_in[4];
    const float* Wv = (const float*)d_in[5];
    const float* bv = (const float*)d_in[6];
    const float* Wo = (const float*)d_in[7];
    const float* bo = (const float*)d_in[8];
    float* out = (float*)d_out;

    const int QKV_SMEM = (3*CC*PITCH + CC*64) * 4;
    cudaFuncSetAttribute(qkv_kernel,   cudaFuncAttributeMaxDynamicSharedMemorySize, QKV_SMEM);
    cudaFuncSetAttribute(stats_kernel, cudaFuncAttributeMaxDynamicSharedMemorySize, ST_SMEM);
    cudaFuncSetAttribute(apply_kernel, cudaFuncAttributeMaxDynamicSharedMemorySize, AP_SMEM);

    qkv_kernel<<<dim3(NN/64, BB), 256, QKV_SMEM>>>(x, Wq, bq, Wk, bk, Wv, bv);
    stats_kernel<<<dim3(NN/128, BB), 256, ST_SMEM>>>();
    apply_kernel<<<dim3(NN/128, BB), 256, AP_SMEM>>>();
    out_kernel<<<dim3(NN/64, BB), 256>>>(Wo, bo, out);
}